// round 1
// baseline (speedup 1.0000x reference)
#include <cuda_runtime.h>
#include <math.h>

#define Bc  2
#define Tc  2048
#define Dc  2048
#define DCc 512
#define DRc 64
#define NHc 16
#define HDc 128
#define BT  (Bc*Tc)

// ---------------- scratch (static device globals; no allocation) ----------------
__device__ float g_ckv[BT*DCc];
__device__ float g_kr [BT*DRc];
__device__ float g_qr [BT*DRc];
__device__ float g_q  [BT*Dc];
__device__ float g_k  [BT*Dc];
__device__ float g_v  [BT*Dc];
__device__ float g_att[BT*Dc];

// ---------------- generic fp32 SGEMM: C[M,N] = A[M,K] @ W[K,N], row-major ------
// 128x128 block, 8x8 per thread, BK=8, 256 threads. M must be a multiple of 128,
// K a multiple of 8; N only needs to be a multiple of 4 (guarded).
__global__ void sgemm128(const float* __restrict__ A, const float* __restrict__ W,
                         float* __restrict__ C, int M, int N, int K) {
    __shared__ float As[8][128];
    __shared__ float Bs[8][128];
    const int tid = threadIdx.x;
    const int bm = blockIdx.y * 128, bn = blockIdx.x * 128;
    const int aRow = tid >> 1, aCol = (tid & 1) * 4;
    const int bRow = tid >> 5, bCol = (tid & 31) * 4;
    const int cr = (tid >> 4) * 8, cc = (tid & 15) * 8;

    float acc[8][8];
#pragma unroll
    for (int i = 0; i < 8; i++)
#pragma unroll
        for (int j = 0; j < 8; j++) acc[i][j] = 0.f;

    for (int k0 = 0; k0 < K; k0 += 8) {
        float4 av = *(const float4*)(A + (size_t)(bm + aRow) * K + k0 + aCol);
        As[aCol + 0][aRow] = av.x;
        As[aCol + 1][aRow] = av.y;
        As[aCol + 2][aRow] = av.z;
        As[aCol + 3][aRow] = av.w;
        float4 bv = make_float4(0.f, 0.f, 0.f, 0.f);
        if (bn + bCol < N)
            bv = *(const float4*)(W + (size_t)(k0 + bRow) * N + bn + bCol);
        *(float4*)&Bs[bRow][bCol] = bv;
        __syncthreads();
#pragma unroll
        for (int kk = 0; kk < 8; kk++) {
            float a[8], b[8];
            *(float4*)&a[0] = *(const float4*)&As[kk][cr];
            *(float4*)&a[4] = *(const float4*)&As[kk][cr + 4];
            *(float4*)&b[0] = *(const float4*)&Bs[kk][cc];
            *(float4*)&b[4] = *(const float4*)&Bs[kk][cc + 4];
#pragma unroll
            for (int i = 0; i < 8; i++)
#pragma unroll
                for (int j = 0; j < 8; j++)
                    acc[i][j] = fmaf(a[i], b[j], acc[i][j]);
        }
        __syncthreads();
    }
#pragma unroll
    for (int i = 0; i < 8; i++) {
        int r = bm + cr + i;
#pragma unroll
        for (int j = 0; j < 8; j += 4) {
            int c = bn + cc + j;
            if (c < N)
                *(float4*)(C + (size_t)r * N + c) =
                    make_float4(acc[i][j], acc[i][j+1], acc[i][j+2], acc[i][j+3]);
        }
    }
}

// ---------------- RoPE (in-place on kr and qr) ---------------------------------
// Angles computed in double to sidestep fp32 range-reduction drift (t up to 2048).
__global__ void rope_kernel(float* __restrict__ kr, float* __restrict__ qr) {
    int bt = blockIdx.x;
    int t  = bt % Tc;
    int i  = threadIdx.x;            // 0..63: [0,32)->kr, [32,64)->qr
    float* row = (i < 32 ? kr : qr) + (size_t)bt * DRc;
    int ii = i & 31;
    double inv = exp(-log(10000.0) * (2.0 * ii) / 64.0);
    double ang = (double)t * inv;
    float cs = (float)cos(ang), sn = (float)sin(ang);
    float x1 = row[ii], x2 = row[ii + 32];
    row[ii]      = x1 * cs - x2 * sn;
    row[ii + 32] = x2 * cs + x1 * sn;
}

// ---------------- entry = concat(ckv, rope(kr)) --------------------------------
__global__ void write_entry(const float* __restrict__ ckv, const float* __restrict__ kr,
                            float* __restrict__ e) {
    int idx = blockIdx.x * blockDim.x + threadIdx.x;
    if (idx >= BT * (DCc + DRc)) return;
    int c  = idx % (DCc + DRc);
    int bt = idx / (DCc + DRc);
    e[idx] = (c < DCc) ? ckv[(size_t)bt * DCc + c]
                       : kr[(size_t)bt * DRc + (c - DCc)];
}

// ---------------- flash attention: dqk = 192 (q||qr vs k||kr), dv = 128, causal -
#define AQK      192
#define QSTRIDE  193     // +1 pad: avoids 192%32==0 row-bank aliasing
#define PSTRIDE  68

__global__ void mla_attn(const float* __restrict__ qg, const float* __restrict__ kg,
                         const float* __restrict__ vg, const float* __restrict__ qrg,
                         const float* __restrict__ krg, float* __restrict__ og) {
    extern __shared__ float sm[];
    float* Qs = sm;                       // [64][193]
    float* Ks = Qs + 64 * QSTRIDE;        // [64][193]
    float* Vs = Ks + 64 * QSTRIDE;        // [64][128]
    float* Ps = Vs + 64 * HDc;            // [64][68]

    const int q0  = blockIdx.x * 64;
    const int h   = blockIdx.y, b = blockIdx.z;
    const int tid = threadIdx.x;
    const int ty  = tid >> 4, tx = tid & 15;
    const float inv_scale = 0.0721687836487032f;   // 1/sqrt(HD+DR) = 1/sqrt(192)

    const float* qb  = qg  + (size_t)b * Tc * Dc + h * HDc;
    const float* kb  = kg  + (size_t)b * Tc * Dc + h * HDc;
    const float* vb  = vg  + (size_t)b * Tc * Dc + h * HDc;
    const float* qrb = qrg + (size_t)b * Tc * DRc;
    const float* krb = krg + (size_t)b * Tc * DRc;

    // Load Q tile: 64 x 192 (first 128 from q, last 64 from qr)
    for (int idx = tid * 4; idx < 64 * AQK; idx += 1024) {
        int r = idx / AQK, c = idx % AQK;
        float4 val = (c < HDc)
            ? *(const float4*)(qb  + (size_t)(q0 + r) * Dc  + c)
            : *(const float4*)(qrb + (size_t)(q0 + r) * DRc + (c - HDc));
        float* d = Qs + r * QSTRIDE + c;
        d[0] = val.x; d[1] = val.y; d[2] = val.z; d[3] = val.w;
    }

    float m[4], l[4], o[4][8];
#pragma unroll
    for (int i = 0; i < 4; i++) {
        m[i] = -INFINITY; l[i] = 0.f;
#pragma unroll
        for (int j = 0; j < 8; j++) o[i][j] = 0.f;
    }

    const int ntiles = blockIdx.x + 1;   // causal: key tiles 0..bx
    for (int jt = 0; jt < ntiles; jt++) {
        const int s0 = jt * 64;
        __syncthreads();                  // previous tile's Vs/Ps fully consumed
        for (int idx = tid * 4; idx < 64 * AQK; idx += 1024) {
            int r = idx / AQK, c = idx % AQK;
            float4 val = (c < HDc)
                ? *(const float4*)(kb  + (size_t)(s0 + r) * Dc  + c)
                : *(const float4*)(krb + (size_t)(s0 + r) * DRc + (c - HDc));
            float* d = Ks + r * QSTRIDE + c;
            d[0] = val.x; d[1] = val.y; d[2] = val.z; d[3] = val.w;
        }
        for (int idx = tid * 4; idx < 64 * HDc; idx += 1024) {
            int r = idx >> 7, c = idx & 127;
            *(float4*)(Vs + r * HDc + c) =
                *(const float4*)(vb + (size_t)(s0 + r) * Dc + c);
        }
        __syncthreads();

        // S = Q * K^T (4x4 per thread over k=192)
        float sacc[4][4];
#pragma unroll
        for (int i = 0; i < 4; i++)
#pragma unroll
            for (int j = 0; j < 4; j++) sacc[i][j] = 0.f;

        for (int kk = 0; kk < AQK; kk++) {
            float qv[4], kv[4];
#pragma unroll
            for (int i = 0; i < 4; i++) qv[i] = Qs[(ty * 4 + i) * QSTRIDE + kk];
#pragma unroll
            for (int j = 0; j < 4; j++) kv[j] = Ks[(tx * 4 + j) * QSTRIDE + kk];
#pragma unroll
            for (int i = 0; i < 4; i++)
#pragma unroll
                for (int j = 0; j < 4; j++)
                    sacc[i][j] = fmaf(qv[i], kv[j], sacc[i][j]);
        }

        const bool diag = (jt == blockIdx.x);
#pragma unroll
        for (int i = 0; i < 4; i++) {
            float mt = -INFINITY;
#pragma unroll
            for (int j = 0; j < 4; j++) {
                float sc = sacc[i][j] * inv_scale;
                if (diag && (s0 + tx * 4 + j > q0 + ty * 4 + i)) sc = -INFINITY;
                sacc[i][j] = sc;
                mt = fmaxf(mt, sc);
            }
#pragma unroll
            for (int off = 8; off > 0; off >>= 1)
                mt = fmaxf(mt, __shfl_xor_sync(0xffffffffu, mt, off));
            float nm = fmaxf(m[i], mt);
            float p0 = expf(sacc[i][0] - nm);
            float p1 = expf(sacc[i][1] - nm);
            float p2 = expf(sacc[i][2] - nm);
            float p3 = expf(sacc[i][3] - nm);
            float rs = p0 + p1 + p2 + p3;
#pragma unroll
            for (int off = 8; off > 0; off >>= 1)
                rs += __shfl_xor_sync(0xffffffffu, rs, off);
            float f = expf(m[i] - nm);
            l[i] = l[i] * f + rs;
            m[i] = nm;
#pragma unroll
            for (int j = 0; j < 8; j++) o[i][j] *= f;
            *(float4*)(Ps + (ty * 4 + i) * PSTRIDE + tx * 4) =
                make_float4(p0, p1, p2, p3);
        }
        __syncthreads();

        // O += P * V   (4 rows x 8 cols per thread)
        for (int s = 0; s < 64; s++) {
            float4 v0 = *(const float4*)(Vs + s * HDc + tx * 8);
            float4 v1 = *(const float4*)(Vs + s * HDc + tx * 8 + 4);
#pragma unroll
            for (int i = 0; i < 4; i++) {
                float p = Ps[(ty * 4 + i) * PSTRIDE + s];
                o[i][0] = fmaf(p, v0.x, o[i][0]);
                o[i][1] = fmaf(p, v0.y, o[i][1]);
                o[i][2] = fmaf(p, v0.z, o[i][2]);
                o[i][3] = fmaf(p, v0.w, o[i][3]);
                o[i][4] = fmaf(p, v1.x, o[i][4]);
                o[i][5] = fmaf(p, v1.y, o[i][5]);
                o[i][6] = fmaf(p, v1.z, o[i][6]);
                o[i][7] = fmaf(p, v1.w, o[i][7]);
            }
        }
    }

#pragma unroll
    for (int i = 0; i < 4; i++) {
        float invl = 1.0f / l[i];
        float* dst = og + ((size_t)b * Tc + q0 + ty * 4 + i) * Dc + h * HDc + tx * 8;
        *(float4*)dst =
            make_float4(o[i][0] * invl, o[i][1] * invl, o[i][2] * invl, o[i][3] * invl);
        *(float4*)(dst + 4) =
            make_float4(o[i][4] * invl, o[i][5] * invl, o[i][6] * invl, o[i][7] * invl);
    }
}

// ---------------- launch -------------------------------------------------------
extern "C" void kernel_launch(void* const* d_in, const int* in_sizes, int n_in,
                              void* d_out, int out_size) {
    const float* x    = (const float*)d_in[0];
    const float* Wkv  = (const float*)d_in[1];
    const float* Wkup = (const float*)d_in[2];
    const float* Wvup = (const float*)d_in[3];
    const float* Wq   = (const float*)d_in[4];
    const float* Wqr  = (const float*)d_in[5];
    const float* Wkr  = (const float*)d_in[6];
    const float* Wo   = (const float*)d_in[7];
    float* out      = (float*)d_out;                 // [B,T,D]
    float* outEntry = out + (size_t)BT * Dc;         // [B,T,DC+DR]

    float *ckv, *kr, *qr, *q, *k, *v, *att;
    cudaGetSymbolAddress((void**)&ckv, g_ckv);
    cudaGetSymbolAddress((void**)&kr,  g_kr);
    cudaGetSymbolAddress((void**)&qr,  g_qr);
    cudaGetSymbolAddress((void**)&q,   g_q);
    cudaGetSymbolAddress((void**)&k,   g_k);
    cudaGetSymbolAddress((void**)&v,   g_v);
    cudaGetSymbolAddress((void**)&att, g_att);

    dim3 blk(256);
    // projections
    sgemm128<<<dim3(DCc / 128, BT / 128), blk>>>(x,   Wkv,  ckv, BT, DCc, Dc);
    sgemm128<<<dim3(Dc  / 128, BT / 128), blk>>>(x,   Wq,   q,   BT, Dc,  Dc);
    sgemm128<<<dim3(1,         BT / 128), blk>>>(x,   Wqr,  qr,  BT, DRc, Dc);
    sgemm128<<<dim3(1,         BT / 128), blk>>>(ckv, Wkr,  kr,  BT, DRc, DCc);
    sgemm128<<<dim3(Dc  / 128, BT / 128), blk>>>(ckv, Wkup, k,   BT, Dc,  DCc);
    sgemm128<<<dim3(Dc  / 128, BT / 128), blk>>>(ckv, Wvup, v,   BT, Dc,  DCc);
    // rope on kr + qr, then entry output
    rope_kernel<<<BT, 64>>>(kr, qr);
    write_entry<<<(BT * (DCc + DRc) + 255) / 256, 256>>>(ckv, kr, outEntry);
    // attention
    size_t smem = (size_t)(64 * QSTRIDE * 2 + 64 * HDc + 64 * PSTRIDE) * sizeof(float);
    cudaFuncSetAttribute(mla_attn, cudaFuncAttributeMaxDynamicSharedMemorySize, (int)smem);
    mla_attn<<<dim3(Tc / 64, NHc, Bc), blk, smem>>>(q, k, v, qr, kr, att);
    // output projection
    sgemm128<<<dim3(Dc / 128, BT / 128), blk>>>(att, Wo, out, BT, Dc, Dc);
}

// round 7
// speedup vs baseline: 1.6407x; 1.6407x over previous
#include <cuda_runtime.h>
#include <cuda_bf16.h>
#include <math.h>
#include <cstdint>

#define Bc  2
#define Tc  2048
#define Dc  2048
#define DCc 512
#define DRc 64
#define NHc 16
#define HDc 128
#define BT  (Bc*Tc)
#define K3D (3*Dc)    /* 6144 */
#define K3C (3*DCc)   /* 1536 */

// ---------------- scratch (static device globals; no allocation) ----------------
__device__ __nv_bfloat16 g_x2  [(size_t)BT*K3D];
__device__ float         g_ckv [(size_t)BT*DCc];
__device__ __nv_bfloat16 g_ckv2[(size_t)BT*K3C];
__device__ float g_kr[BT*DRc], g_qr[BT*DRc];
__device__ float g_q  [(size_t)BT*Dc];
__device__ float g_k  [(size_t)BT*Dc];
__device__ float g_v  [(size_t)BT*Dc];
__device__ float g_att[(size_t)BT*Dc];
__device__ __nv_bfloat16 g_att2[(size_t)BT*K3D];
__device__ __nv_bfloat16 w_kv [(size_t)DCc*K3D];
__device__ __nv_bfloat16 w_q  [(size_t)Dc *K3D];
__device__ __nv_bfloat16 w_qr [(size_t)DRc*K3D];
__device__ __nv_bfloat16 w_kr [(size_t)DRc*K3C];
__device__ __nv_bfloat16 w_kup[(size_t)Dc *K3C];
__device__ __nv_bfloat16 w_vup[(size_t)Dc *K3C];
__device__ __nv_bfloat16 w_o  [(size_t)Dc *K3D];

// ---------------- helpers -------------------------------------------------------
__device__ __forceinline__ uint32_t smem_u32(const void* p) {
    uint32_t a;
    asm("{ .reg .u64 t; cvta.to.shared.u64 t, %1; cvt.u32.u64 %0, t; }" : "=r"(a) : "l"(p));
    return a;
}
__device__ __forceinline__ void cp16(uint32_t dst, const void* src) {
    asm volatile("cp.async.cg.shared.global [%0], [%1], 16;" :: "r"(dst), "l"(src));
}
#define CP_COMMIT() asm volatile("cp.async.commit_group;" ::: "memory")
#define CP_WAIT0()  asm volatile("cp.async.wait_group 0;" ::: "memory")
#define LDSM4(r, a) \
    asm volatile("ldmatrix.sync.aligned.m8n8.x4.shared.b16 {%0,%1,%2,%3}, [%4];" \
        : "=r"((r)[0]), "=r"((r)[1]), "=r"((r)[2]), "=r"((r)[3]) : "r"(a))
#define MMA16816(d, a, b) \
    asm volatile("mma.sync.aligned.m16n8k16.row.col.f32.bf16.bf16.f32 " \
        "{%0,%1,%2,%3}, {%4,%5,%6,%7}, {%8,%9}, {%0,%1,%2,%3};" \
        : "+f"((d)[0]), "+f"((d)[1]), "+f"((d)[2]), "+f"((d)[3]) \
        : "r"((a)[0]), "r"((a)[1]), "r"((a)[2]), "r"((a)[3]), "r"((b)[0]), "r"((b)[1]))

// ---------------- conversion kernels --------------------------------------------
// A-side split: out[m][3k+0]=hi, [3k+1]=hi, [3k+2]=lo
__global__ void split3(const float* __restrict__ A, __nv_bfloat16* __restrict__ O, int total, int K) {
    int idx = blockIdx.x * blockDim.x + threadIdx.x;
    if (idx >= total) return;
    int k = idx % K, m = idx / K;
    float v = A[idx];
    __nv_bfloat16 h = __float2bfloat16_rn(v);
    __nv_bfloat16 l = __float2bfloat16_rn(v - __bfloat162float(h));
    size_t o = (size_t)m * (3 * K) + 3 * k;
    O[o] = h; O[o + 1] = h; O[o + 2] = l;
}
// B-side transpose+split: W[K,N] -> O[N][3K], [3k+0]=hi, [3k+1]=lo, [3k+2]=hi
__global__ void tsplit3(const float* __restrict__ W, __nv_bfloat16* __restrict__ O, int K, int N) {
    __shared__ float t[32][33];
    int n0 = blockIdx.x * 32, k0 = blockIdx.y * 32;
    int tx = threadIdx.x, ty = threadIdx.y;
    for (int i = ty; i < 32; i += 8)
        t[i][tx] = W[(size_t)(k0 + i) * N + n0 + tx];
    __syncthreads();
    for (int i = ty; i < 32; i += 8) {
        int n = n0 + i, k = k0 + tx;
        float v = t[tx][i];
        __nv_bfloat16 h = __float2bfloat16_rn(v);
        __nv_bfloat16 l = __float2bfloat16_rn(v - __bfloat162float(h));
        size_t o = (size_t)n * (3 * K) + 3 * k;
        O[o] = h; O[o + 1] = l; O[o + 2] = h;
    }
}

// ---------------- mma.sync GEMM: C[M,N] fp32 = A[M,K]bf16 @ B[N,K]bf16^T ---------
// 128 x BN tile, BK=64, cp.async double buffer, 8 warps (2x4), warp tile 64x(BN/4).
template <int BN>
__global__ void __launch_bounds__(256) gemm_mma(
    const __nv_bfloat16* __restrict__ A, const __nv_bfloat16* __restrict__ B,
    float* __restrict__ C, int M, int N, int K)
{
    constexpr int BM = 128, BK = 64;
    constexpr int ST = 72;                 // padded row stride (bf16): 144B -> conflict-free
    constexpr int WN = BN / 4;             // warp n-extent (32 or 16)
    constexpr int NT = WN / 8;             // n mma tiles per warp (4 or 2)
    extern __shared__ __nv_bfloat16 smem[];
    __nv_bfloat16* As = smem;                        // [2][BM][ST]
    __nv_bfloat16* Bs = smem + 2 * BM * ST;          // [2][BN][ST]

    const int tid = threadIdx.x, lane = tid & 31, wid = tid >> 5;
    const int wm = wid >> 2, wn = wid & 3;
    const int bm = blockIdx.y * BM, bn = blockIdx.x * BN;

    float acc[4][NT][4];
#pragma unroll
    for (int i = 0; i < 4; i++)
#pragma unroll
        for (int j = 0; j < NT; j++)
#pragma unroll
            for (int r = 0; r < 4; r++) acc[i][j][r] = 0.f;

    const uint32_t asb = smem_u32(As), bsb = smem_u32(Bs);

    auto loadStage = [&](int it, int buf) {
        const __nv_bfloat16* Ag = A + (size_t)bm * K + it * BK;
        uint32_t ad = asb + buf * BM * ST * 2;
#pragma unroll
        for (int i = 0; i < 4; i++) {
            int c = tid + i * 256, r = c >> 3, cc = c & 7;
            cp16(ad + (r * ST + cc * 8) * 2, Ag + (size_t)r * K + cc * 8);
        }
        const __nv_bfloat16* Bg = B + (size_t)bn * K + it * BK;
        uint32_t bd = bsb + buf * BN * ST * 2;
#pragma unroll
        for (int i = 0; i < BN / 32; i++) {
            int c = tid + i * 256, r = c >> 3, cc = c & 7;
            cp16(bd + (r * ST + cc * 8) * 2, Bg + (size_t)r * K + cc * 8);
        }
        CP_COMMIT();
    };

    loadStage(0, 0);
    const int nIter = K / BK;
    for (int it = 0; it < nIter; it++) {
        const int buf = it & 1;
        CP_WAIT0();
        __syncthreads();
        if (it + 1 < nIter) loadStage(it + 1, buf ^ 1);

        const uint32_t ab = asb + buf * BM * ST * 2;
        const uint32_t bb = bsb + buf * BN * ST * 2;
#pragma unroll
        for (int ks = 0; ks < BK / 16; ks++) {
            uint32_t a[4][4];
#pragma unroll
            for (int mi = 0; mi < 4; mi++) {
                int row = wm * 64 + mi * 16 + (lane & 15);
                uint32_t addr = ab + (row * ST + ks * 16 + ((lane >> 4) << 3)) * 2;
                LDSM4(a[mi], addr);
            }
            uint32_t b[NT][2];
#pragma unroll
            for (int nj = 0; nj < NT / 2; nj++) {
                int row = wn * WN + nj * 16 + ((lane >> 4) << 3) + (lane & 7);
                uint32_t addr = bb + (row * ST + ks * 16 + (((lane >> 3) & 1) << 3)) * 2;
                uint32_t r4[4];
                LDSM4(r4, addr);
                b[nj * 2][0] = r4[0]; b[nj * 2][1] = r4[1];
                b[nj * 2 + 1][0] = r4[2]; b[nj * 2 + 1][1] = r4[3];
            }
#pragma unroll
            for (int mi = 0; mi < 4; mi++)
#pragma unroll
                for (int ni = 0; ni < NT; ni++)
                    MMA16816(acc[mi][ni], a[mi], b[ni]);
        }
    }

    // epilogue
#pragma unroll
    for (int mi = 0; mi < 4; mi++) {
        int row0 = bm + wm * 64 + mi * 16 + (lane >> 2);
#pragma unroll
        for (int ni = 0; ni < NT; ni++) {
            int col = bn + wn * WN + ni * 8 + (lane & 3) * 2;
            *(float2*)(C + (size_t)row0 * N + col)       = make_float2(acc[mi][ni][0], acc[mi][ni][1]);
            *(float2*)(C + (size_t)(row0 + 8) * N + col) = make_float2(acc[mi][ni][2], acc[mi][ni][3]);
        }
    }
}

// ---------------- RoPE (in-place on kr and qr) -----------------------------------
__global__ void rope_kernel(float* __restrict__ kr, float* __restrict__ qr) {
    int bt = blockIdx.x;
    int t  = bt % Tc;
    int i  = threadIdx.x;
    float* row = (i < 32 ? kr : qr) + (size_t)bt * DRc;
    int ii = i & 31;
    double inv = exp(-log(10000.0) * (2.0 * ii) / 64.0);
    double ang = (double)t * inv;
    float cs = (float)cos(ang), sn = (float)sin(ang);
    float x1 = row[ii], x2 = row[ii + 32];
    row[ii]      = x1 * cs - x2 * sn;
    row[ii + 32] = x2 * cs + x1 * sn;
}

// ---------------- entry = concat(ckv, rope(kr)) ----------------------------------
__global__ void write_entry(const float* __restrict__ ckv, const float* __restrict__ kr,
                            float* __restrict__ e) {
    int idx = blockIdx.x * blockDim.x + threadIdx.x;
    if (idx >= BT * (DCc + DRc)) return;
    int c  = idx % (DCc + DRc);
    int bt = idx / (DCc + DRc);
    e[idx] = (c < DCc) ? ckv[(size_t)bt * DCc + c]
                       : kr[(size_t)bt * DRc + (c - DCc)];
}

// ---------------- flash attention (fp32 SIMT) ------------------------------------
#define AQK      192
#define QSTRIDE  193
#define PSTRIDE  68

__global__ void mla_attn(const float* __restrict__ qg, const float* __restrict__ kg,
                         const float* __restrict__ vg, const float* __restrict__ qrg,
                         const float* __restrict__ krg, float* __restrict__ og) {
    extern __shared__ float sm[];
    float* Qs = sm;
    float* Ks = Qs + 64 * QSTRIDE;
    float* Vs = Ks + 64 * QSTRIDE;
    float* Ps = Vs + 64 * HDc;

    const int q0  = blockIdx.x * 64;
    const int h   = blockIdx.y, b = blockIdx.z;
    const int tid = threadIdx.x;
    const int ty  = tid >> 4, tx = tid & 15;
    const float inv_scale = 0.0721687836487032f;

    const float* qb  = qg  + (size_t)b * Tc * Dc + h * HDc;
    const float* kb  = kg  + (size_t)b * Tc * Dc + h * HDc;
    const float* vb  = vg  + (size_t)b * Tc * Dc + h * HDc;
    const float* qrb = qrg + (size_t)b * Tc * DRc;
    const float* krb = krg + (size_t)b * Tc * DRc;

    for (int idx = tid * 4; idx < 64 * AQK; idx += 1024) {
        int r = idx / AQK, c = idx % AQK;
        float4 val = (c < HDc)
            ? *(const float4*)(qb  + (size_t)(q0 + r) * Dc  + c)
            : *(const float4*)(qrb + (size_t)(q0 + r) * DRc + (c - HDc));
        float* d = Qs + r * QSTRIDE + c;
        d[0] = val.x; d[1] = val.y; d[2] = val.z; d[3] = val.w;
    }

    float m[4], l[4], o[4][8];
#pragma unroll
    for (int i = 0; i < 4; i++) {
        m[i] = -INFINITY; l[i] = 0.f;
#pragma unroll
        for (int j = 0; j < 8; j++) o[i][j] = 0.f;
    }

    const int ntiles = blockIdx.x + 1;
    for (int jt = 0; jt < ntiles; jt++) {
        const int s0 = jt * 64;
        __syncthreads();
        for (int idx = tid * 4; idx < 64 * AQK; idx += 1024) {
            int r = idx / AQK, c = idx % AQK;
            float4 val = (c < HDc)
                ? *(const float4*)(kb  + (size_t)(s0 + r) * Dc  + c)
                : *(const float4*)(krb + (size_t)(s0 + r) * DRc + (c - HDc));
            float* d = Ks + r * QSTRIDE + c;
            d[0] = val.x; d[1] = val.y; d[2] = val.z; d[3] = val.w;
        }
        for (int idx = tid * 4; idx < 64 * HDc; idx += 1024) {
            int r = idx >> 7, c = idx & 127;
            *(float4*)(Vs + r * HDc + c) =
                *(const float4*)(vb + (size_t)(s0 + r) * Dc + c);
        }
        __syncthreads();

        float sacc[4][4];
#pragma unroll
        for (int i = 0; i < 4; i++)
#pragma unroll
            for (int j = 0; j < 4; j++) sacc[i][j] = 0.f;

        for (int kk = 0; kk < AQK; kk++) {
            float qv[4], kv[4];
#pragma unroll
            for (int i = 0; i < 4; i++) qv[i] = Qs[(ty * 4 + i) * QSTRIDE + kk];
#pragma unroll
            for (int j = 0; j < 4; j++) kv[j] = Ks[(tx * 4 + j) * QSTRIDE + kk];
#pragma unroll
            for (int i = 0; i < 4; i++)
#pragma unroll
                for (int j = 0; j < 4; j++)
                    sacc[i][j] = fmaf(qv[i], kv[j], sacc[i][j]);
        }

        const bool diag = (jt == blockIdx.x);
#pragma unroll
        for (int i = 0; i < 4; i++) {
            float mt = -INFINITY;
#pragma unroll
            for (int j = 0; j < 4; j++) {
                float sc = sacc[i][j] * inv_scale;
                if (diag && (s0 + tx * 4 + j > q0 + ty * 4 + i)) sc = -INFINITY;
                sacc[i][j] = sc;
                mt = fmaxf(mt, sc);
            }
#pragma unroll
            for (int off = 8; off > 0; off >>= 1)
                mt = fmaxf(mt, __shfl_xor_sync(0xffffffffu, mt, off));
            float nm = fmaxf(m[i], mt);
            float p0 = expf(sacc[i][0] - nm);
            float p1 = expf(sacc[i][1] - nm);
            float p2 = expf(sacc[i][2] - nm);
            float p3 = expf(sacc[i][3] - nm);
            float rs = p0 + p1 + p2 + p3;
#pragma unroll
            for (int off = 8; off > 0; off >>= 1)
                rs += __shfl_xor_sync(0xffffffffu, rs, off);
            float f = expf(m[i] - nm);
            l[i] = l[i] * f + rs;
            m[i] = nm;
#pragma unroll
            for (int j = 0; j < 8; j++) o[i][j] *= f;
            *(float4*)(Ps + (ty * 4 + i) * PSTRIDE + tx * 4) =
                make_float4(p0, p1, p2, p3);
        }
        __syncthreads();

        for (int s = 0; s < 64; s++) {
            float4 v0 = *(const float4*)(Vs + s * HDc + tx * 8);
            float4 v1 = *(const float4*)(Vs + s * HDc + tx * 8 + 4);
#pragma unroll
            for (int i = 0; i < 4; i++) {
                float p = Ps[(ty * 4 + i) * PSTRIDE + s];
                o[i][0] = fmaf(p, v0.x, o[i][0]);
                o[i][1] = fmaf(p, v0.y, o[i][1]);
                o[i][2] = fmaf(p, v0.z, o[i][2]);
                o[i][3] = fmaf(p, v0.w, o[i][3]);
                o[i][4] = fmaf(p, v1.x, o[i][4]);
                o[i][5] = fmaf(p, v1.y, o[i][5]);
                o[i][6] = fmaf(p, v1.z, o[i][6]);
                o[i][7] = fmaf(p, v1.w, o[i][7]);
            }
        }
    }

#pragma unroll
    for (int i = 0; i < 4; i++) {
        float invl = 1.0f / l[i];
        float* dst = og + ((size_t)b * Tc + q0 + ty * 4 + i) * Dc + h * HDc + tx * 8;
        *(float4*)dst =
            make_float4(o[i][0] * invl, o[i][1] * invl, o[i][2] * invl, o[i][3] * invl);
        *(float4*)(dst + 4) =
            make_float4(o[i][4] * invl, o[i][5] * invl, o[i][6] * invl, o[i][7] * invl);
    }
}

// ---------------- launch ---------------------------------------------------------
extern "C" void kernel_launch(void* const* d_in, const int* in_sizes, int n_in,
                              void* d_out, int out_size) {
    const float* x    = (const float*)d_in[0];
    const float* Wkv  = (const float*)d_in[1];
    const float* Wkup = (const float*)d_in[2];
    const float* Wvup = (const float*)d_in[3];
    const float* Wq   = (const float*)d_in[4];
    const float* Wqr  = (const float*)d_in[5];
    const float* Wkr  = (const float*)d_in[6];
    const float* Wo   = (const float*)d_in[7];
    float* out      = (float*)d_out;
    float* outEntry = out + (size_t)BT * Dc;

    float *ckv, *kr, *qr, *q, *k, *v, *att;
    __nv_bfloat16 *x2, *ckv2, *att2, *wkv, *wq, *wqr, *wkr, *wkup, *wvup, *wo;
    cudaGetSymbolAddress((void**)&ckv,  g_ckv);
    cudaGetSymbolAddress((void**)&kr,   g_kr);
    cudaGetSymbolAddress((void**)&qr,   g_qr);
    cudaGetSymbolAddress((void**)&q,    g_q);
    cudaGetSymbolAddress((void**)&k,    g_k);
    cudaGetSymbolAddress((void**)&v,    g_v);
    cudaGetSymbolAddress((void**)&att,  g_att);
    cudaGetSymbolAddress((void**)&x2,   g_x2);
    cudaGetSymbolAddress((void**)&ckv2, g_ckv2);
    cudaGetSymbolAddress((void**)&att2, g_att2);
    cudaGetSymbolAddress((void**)&wkv,  w_kv);
    cudaGetSymbolAddress((void**)&wq,   w_q);
    cudaGetSymbolAddress((void**)&wqr,  w_qr);
    cudaGetSymbolAddress((void**)&wkr,  w_kr);
    cudaGetSymbolAddress((void**)&wkup, w_kup);
    cudaGetSymbolAddress((void**)&wvup, w_vup);
    cudaGetSymbolAddress((void**)&wo,   w_o);

    const int SM128 = (2 * 128 + 2 * 128) * 72 * 2;   // 73728
    const int SM64  = (2 * 128 + 2 * 64)  * 72 * 2;   // 55296
    cudaFuncSetAttribute(gemm_mma<128>, cudaFuncAttributeMaxDynamicSharedMemorySize, SM128);
    cudaFuncSetAttribute(gemm_mma<64>,  cudaFuncAttributeMaxDynamicSharedMemorySize, SM64);

    dim3 tb(32, 8);
    // weight transpose+split (B-side pairing: hi, lo, hi)
    tsplit3<<<dim3(DCc / 32, Dc  / 32), tb>>>(Wkv,  wkv,  Dc,  DCc);
    tsplit3<<<dim3(Dc  / 32, Dc  / 32), tb>>>(Wq,   wq,   Dc,  Dc);
    tsplit3<<<dim3(DRc / 32, Dc  / 32), tb>>>(Wqr,  wqr,  Dc,  DRc);
    tsplit3<<<dim3(DRc / 32, DCc / 32), tb>>>(Wkr,  wkr,  DCc, DRc);
    tsplit3<<<dim3(Dc  / 32, DCc / 32), tb>>>(Wkup, wkup, DCc, Dc);
    tsplit3<<<dim3(Dc  / 32, DCc / 32), tb>>>(Wvup, wvup, DCc, Dc);
    tsplit3<<<dim3(Dc  / 32, Dc  / 32), tb>>>(Wo,   wo,   Dc,  Dc);
    // activation split (A-side pairing: hi, hi, lo)
    split3<<<(BT * Dc + 255) / 256, 256>>>(x, x2, BT * Dc, Dc);

    // projections on mma.sync tensor cores
    gemm_mma<128><<<dim3(DCc / 128, BT / 128), 256, SM128>>>(x2, wkv, ckv, BT, DCc, K3D);
    gemm_mma<128><<<dim3(Dc  / 128, BT / 128), 256, SM128>>>(x2, wq,  q,   BT, Dc,  K3D);
    gemm_mma<64> <<<dim3(1,         BT / 128), 256, SM64 >>>(x2, wqr, qr,  BT, DRc, K3D);
    split3<<<(BT * DCc + 255) / 256, 256>>>(ckv, ckv2, BT * DCc, DCc);
    gemm_mma<64> <<<dim3(1,         BT / 128), 256, SM64 >>>(ckv2, wkr,  kr, BT, DRc, K3C);
    gemm_mma<128><<<dim3(Dc  / 128, BT / 128), 256, SM128>>>(ckv2, wkup, k,  BT, Dc,  K3C);
    gemm_mma<128><<<dim3(Dc  / 128, BT / 128), 256, SM128>>>(ckv2, wvup, v,  BT, Dc,  K3C);

    // rope + entry output
    rope_kernel<<<BT, 64>>>(kr, qr);
    write_entry<<<(BT * (DCc + DRc) + 255) / 256, 256>>>(ckv, kr, outEntry);

    // attention (fp32)
    size_t smem = (size_t)(64 * QSTRIDE * 2 + 64 * HDc + 64 * PSTRIDE) * sizeof(float);
    cudaFuncSetAttribute(mla_attn, cudaFuncAttributeMaxDynamicSharedMemorySize, (int)smem);
    mla_attn<<<dim3(Tc / 64, NHc, Bc), 256, smem>>>(q, k, v, qr, kr, att);

    // output projection
    split3<<<(BT * Dc + 255) / 256, 256>>>(att, att2, BT * Dc, Dc);
    gemm_mma<128><<<dim3(Dc / 128, BT / 128), 256, SM128>>>(att2, wo, out, BT, Dc, K3D);
}

// round 9
// speedup vs baseline: 2.6587x; 1.6205x over previous
#include <cuda_runtime.h>
#include <cuda_bf16.h>
#include <math.h>
#include <cstdint>

#define Bc  2
#define Tc  2048
#define Dc  2048
#define DCc 512
#define DRc 64
#define NHc 16
#define HDc 128
#define BT  (Bc*Tc)
#define K3D (3*Dc)    /* 6144 */
#define K3C (3*DCc)   /* 1536 */
#define AQK 192
#define QK_K 576      /* 3*192 */

// ---------------- scratch (static device globals; no allocation) ----------------
__device__ __nv_bfloat16 g_x2  [(size_t)BT*K3D];
__device__ float         g_ckv [(size_t)BT*DCc];
__device__ __nv_bfloat16 g_ckv2[(size_t)BT*K3C];
__device__ float g_kr[BT*DRc], g_qr[BT*DRc];
__device__ float g_q  [(size_t)BT*Dc];
__device__ float g_k  [(size_t)BT*Dc];
__device__ float g_v  [(size_t)BT*Dc];
__device__ float g_att[(size_t)BT*Dc];
__device__ __nv_bfloat16 g_att2[(size_t)BT*K3D];
__device__ __nv_bfloat16 w_kv [(size_t)DCc*K3D];
__device__ __nv_bfloat16 w_q  [(size_t)Dc *K3D];
__device__ __nv_bfloat16 w_qr [(size_t)DRc*K3D];
__device__ __nv_bfloat16 w_kr [(size_t)DRc*K3C];
__device__ __nv_bfloat16 w_kup[(size_t)Dc *K3C];
__device__ __nv_bfloat16 w_vup[(size_t)Dc *K3C];
__device__ __nv_bfloat16 w_o  [(size_t)Dc *K3D];
// attention operands (per-head split layouts)
__device__ __nv_bfloat16 g_Q2[(size_t)Bc*NHc*Tc*QK_K];
__device__ __nv_bfloat16 g_K2[(size_t)Bc*NHc*Tc*QK_K];
__device__ __nv_bfloat16 g_V2[(size_t)Bc*NHc*3*Tc*HDc];

// ---------------- helpers -------------------------------------------------------
__device__ __forceinline__ uint32_t smem_u32(const void* p) {
    uint32_t a;
    asm("{ .reg .u64 t; cvta.to.shared.u64 t, %1; cvt.u32.u64 %0, t; }" : "=r"(a) : "l"(p));
    return a;
}
__device__ __forceinline__ void cp16(uint32_t dst, const void* src) {
    asm volatile("cp.async.cg.shared.global [%0], [%1], 16;" :: "r"(dst), "l"(src));
}
#define CP_COMMIT() asm volatile("cp.async.commit_group;" ::: "memory")
#define CP_WAIT0()  asm volatile("cp.async.wait_group 0;" ::: "memory")
#define CP_WAIT1()  asm volatile("cp.async.wait_group 1;" ::: "memory")
#define LDSM4(r, a) \
    asm volatile("ldmatrix.sync.aligned.m8n8.x4.shared.b16 {%0,%1,%2,%3}, [%4];" \
        : "=r"((r)[0]), "=r"((r)[1]), "=r"((r)[2]), "=r"((r)[3]) : "r"(a))
#define LDSM4T(r, a) \
    asm volatile("ldmatrix.sync.aligned.m8n8.x4.trans.shared.b16 {%0,%1,%2,%3}, [%4];" \
        : "=r"((r)[0]), "=r"((r)[1]), "=r"((r)[2]), "=r"((r)[3]) : "r"(a))
#define MMA16816(d, a, b0, b1) \
    asm volatile("mma.sync.aligned.m16n8k16.row.col.f32.bf16.bf16.f32 " \
        "{%0,%1,%2,%3}, {%4,%5,%6,%7}, {%8,%9}, {%0,%1,%2,%3};" \
        : "+f"((d)[0]), "+f"((d)[1]), "+f"((d)[2]), "+f"((d)[3]) \
        : "r"((a)[0]), "r"((a)[1]), "r"((a)[2]), "r"((a)[3]), "r"(b0), "r"(b1))
#define STS32(a, v) asm volatile("st.shared.b32 [%0], %1;" :: "r"(a), "r"(v) : "memory")
__device__ __forceinline__ uint32_t bfpack(float a, float b) {
    __nv_bfloat162 t = __floats2bfloat162_rn(a, b);
    return *(uint32_t*)&t;
}

// ---------------- conversion kernels --------------------------------------------
__global__ void split3(const float* __restrict__ A, __nv_bfloat16* __restrict__ O, int total, int K) {
    int idx = blockIdx.x * blockDim.x + threadIdx.x;
    if (idx >= total) return;
    int k = idx % K, m = idx / K;
    float v = A[idx];
    __nv_bfloat16 h = __float2bfloat16_rn(v);
    __nv_bfloat16 l = __float2bfloat16_rn(v - __bfloat162float(h));
    size_t o = (size_t)m * (3 * K) + 3 * k;
    O[o] = h; O[o + 1] = h; O[o + 2] = l;
}
__global__ void tsplit3(const float* __restrict__ W, __nv_bfloat16* __restrict__ O, int K, int N) {
    __shared__ float t[32][33];
    int n0 = blockIdx.x * 32, k0 = blockIdx.y * 32;
    int tx = threadIdx.x, ty = threadIdx.y;
    for (int i = ty; i < 32; i += 8)
        t[i][tx] = W[(size_t)(k0 + i) * N + n0 + tx];
    __syncthreads();
    for (int i = ty; i < 32; i += 8) {
        int n = n0 + i, k = k0 + tx;
        float v = t[tx][i];
        __nv_bfloat16 h = __float2bfloat16_rn(v);
        __nv_bfloat16 l = __float2bfloat16_rn(v - __bfloat162float(h));
        size_t o = (size_t)n * (3 * K) + 3 * k;
        O[o] = h; O[o + 1] = l; O[o + 2] = h;
    }
}

// ---------------- mma.sync GEMM (validated round 7) ------------------------------
template <int BN>
__global__ void __launch_bounds__(256) gemm_mma(
    const __nv_bfloat16* __restrict__ A, const __nv_bfloat16* __restrict__ B,
    float* __restrict__ C, int M, int N, int K)
{
    constexpr int BM = 128, BK = 64;
    constexpr int ST = 72;
    constexpr int WN = BN / 4;
    constexpr int NT = WN / 8;
    extern __shared__ __nv_bfloat16 smem[];
    __nv_bfloat16* As = smem;
    __nv_bfloat16* Bs = smem + 2 * BM * ST;

    const int tid = threadIdx.x, lane = tid & 31, wid = tid >> 5;
    const int wm = wid >> 2, wn = wid & 3;
    const int bm = blockIdx.y * BM, bn = blockIdx.x * BN;

    float acc[4][NT][4];
#pragma unroll
    for (int i = 0; i < 4; i++)
#pragma unroll
        for (int j = 0; j < NT; j++)
#pragma unroll
            for (int r = 0; r < 4; r++) acc[i][j][r] = 0.f;

    const uint32_t asb = smem_u32(As), bsb = smem_u32(Bs);

    auto loadStage = [&](int it, int buf) {
        const __nv_bfloat16* Ag = A + (size_t)bm * K + it * BK;
        uint32_t ad = asb + buf * BM * ST * 2;
#pragma unroll
        for (int i = 0; i < 4; i++) {
            int c = tid + i * 256, r = c >> 3, cc = c & 7;
            cp16(ad + (r * ST + cc * 8) * 2, Ag + (size_t)r * K + cc * 8);
        }
        const __nv_bfloat16* Bg = B + (size_t)bn * K + it * BK;
        uint32_t bd = bsb + buf * BN * ST * 2;
#pragma unroll
        for (int i = 0; i < BN / 32; i++) {
            int c = tid + i * 256, r = c >> 3, cc = c & 7;
            cp16(bd + (r * ST + cc * 8) * 2, Bg + (size_t)r * K + cc * 8);
        }
        CP_COMMIT();
    };

    loadStage(0, 0);
    const int nIter = K / BK;
    for (int it = 0; it < nIter; it++) {
        const int buf = it & 1;
        CP_WAIT0();
        __syncthreads();
        if (it + 1 < nIter) loadStage(it + 1, buf ^ 1);

        const uint32_t ab = asb + buf * BM * ST * 2;
        const uint32_t bb = bsb + buf * BN * ST * 2;
#pragma unroll
        for (int ks = 0; ks < BK / 16; ks++) {
            uint32_t a[4][4];
#pragma unroll
            for (int mi = 0; mi < 4; mi++) {
                int row = wm * 64 + mi * 16 + (lane & 15);
                uint32_t addr = ab + (row * ST + ks * 16 + ((lane >> 4) << 3)) * 2;
                LDSM4(a[mi], addr);
            }
            uint32_t b[NT][2];
#pragma unroll
            for (int nj = 0; nj < NT / 2; nj++) {
                int row = wn * WN + nj * 16 + ((lane >> 4) << 3) + (lane & 7);
                uint32_t addr = bb + (row * ST + ks * 16 + (((lane >> 3) & 1) << 3)) * 2;
                uint32_t r4[4];
                LDSM4(r4, addr);
                b[nj * 2][0] = r4[0]; b[nj * 2][1] = r4[1];
                b[nj * 2 + 1][0] = r4[2]; b[nj * 2 + 1][1] = r4[3];
            }
#pragma unroll
            for (int mi = 0; mi < 4; mi++)
#pragma unroll
                for (int ni = 0; ni < NT; ni++)
                    MMA16816(acc[mi][ni], a[mi], b[ni][0], b[ni][1]);
        }
        __syncthreads();
    }

#pragma unroll
    for (int mi = 0; mi < 4; mi++) {
        int row0 = bm + wm * 64 + mi * 16 + (lane >> 2);
#pragma unroll
        for (int ni = 0; ni < NT; ni++) {
            int col = bn + wn * WN + ni * 8 + (lane & 3) * 2;
            *(float2*)(C + (size_t)row0 * N + col)       = make_float2(acc[mi][ni][0], acc[mi][ni][1]);
            *(float2*)(C + (size_t)(row0 + 8) * N + col) = make_float2(acc[mi][ni][2], acc[mi][ni][3]);
        }
    }
}

// ---------------- RoPE -----------------------------------------------------------
__global__ void rope_kernel(float* __restrict__ kr, float* __restrict__ qr) {
    int bt = blockIdx.x;
    int t  = bt % Tc;
    int i  = threadIdx.x;
    float* row = (i < 32 ? kr : qr) + (size_t)bt * DRc;
    int ii = i & 31;
    double inv = exp(-log(10000.0) * (2.0 * ii) / 64.0);
    double ang = (double)t * inv;
    float cs = (float)cos(ang), sn = (float)sin(ang);
    float x1 = row[ii], x2 = row[ii + 32];
    row[ii]      = x1 * cs - x2 * sn;
    row[ii + 32] = x2 * cs + x1 * sn;
}

// ---------------- entry = concat(ckv, rope(kr)) ----------------------------------
__global__ void write_entry(const float* __restrict__ ckv, const float* __restrict__ kr,
                            float* __restrict__ e) {
    int idx = blockIdx.x * blockDim.x + threadIdx.x;
    if (idx >= BT * (DCc + DRc)) return;
    int c  = idx % (DCc + DRc);
    int bt = idx / (DCc + DRc);
    e[idx] = (c < DCc) ? ckv[(size_t)bt * DCc + c]
                       : kr[(size_t)bt * DRc + (c - DCc)];
}

// ---------------- attention prep: per-head split operands ------------------------
// Q2[b,h,t][3dk..] = (qh,qh,ql)  K2: (kh,kl,kh)   V2[b,h,3t+j][d]: j0=vh, j1=vl, j2=vh
__global__ void prep_attn(const float* __restrict__ q, const float* __restrict__ k,
                          const float* __restrict__ v, const float* __restrict__ qr,
                          const float* __restrict__ kr,
                          __nv_bfloat16* __restrict__ Q2, __nv_bfloat16* __restrict__ K2,
                          __nv_bfloat16* __restrict__ V2) {
    int bid = blockIdx.x;               // bt*NH + h
    int bt = bid / NHc, h = bid % NHc;
    int b = bt / Tc, t = bt % Tc;
    int c = threadIdx.x;                // 0..191
    size_t rowQK = ((size_t)(b * NHc + h) * Tc + t) * QK_K;
    {
        float qv = (c < HDc) ? q[(size_t)bt * Dc + h * HDc + c] : qr[(size_t)bt * DRc + (c - HDc)];
        __nv_bfloat16 hh = __float2bfloat16_rn(qv);
        __nv_bfloat16 ll = __float2bfloat16_rn(qv - __bfloat162float(hh));
        Q2[rowQK + 3 * c] = hh; Q2[rowQK + 3 * c + 1] = hh; Q2[rowQK + 3 * c + 2] = ll;
        float kv = (c < HDc) ? k[(size_t)bt * Dc + h * HDc + c] : kr[(size_t)bt * DRc + (c - HDc)];
        hh = __float2bfloat16_rn(kv);
        ll = __float2bfloat16_rn(kv - __bfloat162float(hh));
        K2[rowQK + 3 * c] = hh; K2[rowQK + 3 * c + 1] = ll; K2[rowQK + 3 * c + 2] = hh;
    }
    if (c < HDc) {
        float vv = v[(size_t)bt * Dc + h * HDc + c];
        __nv_bfloat16 hh = __float2bfloat16_rn(vv);
        __nv_bfloat16 ll = __float2bfloat16_rn(vv - __bfloat162float(hh));
        size_t base = ((size_t)(b * NHc + h) * 3 * Tc + 3 * t) * HDc + c;
        V2[base] = hh; V2[base + HDc] = ll; V2[base + 2 * HDc] = hh;
    }
}

// ---------------- tensor-core flash attention ------------------------------------
// BQ=64, BS=64; QK over k=576 (split bf16), PV over k=192 (split bf16).
#define QS_ST 584    /* Qs/Ks row stride (bf16) */
#define VS_ST 136    /* Vs row stride */
#define PS_ST 200    /* Ps row stride */

__global__ void __launch_bounds__(128) mla_attn_tc(
    const __nv_bfloat16* __restrict__ Q2, const __nv_bfloat16* __restrict__ K2,
    const __nv_bfloat16* __restrict__ V2, float* __restrict__ og)
{
    extern __shared__ __nv_bfloat16 sm2[];
    __nv_bfloat16* Qs = sm2;                    // [64][584]
    __nv_bfloat16* Ks = Qs + 64 * QS_ST;        // [64][584]
    __nv_bfloat16* Vs = Ks + 64 * QS_ST;        // [192][136]
    __nv_bfloat16* Ps = Vs + 192 * VS_ST;       // [64][200]

    const int tid = threadIdx.x, lane = tid & 31, wq = tid >> 5;
    const int q0 = blockIdx.x * 64, h = blockIdx.y, b = blockIdx.z;
    const uint32_t qsb = smem_u32(Qs), ksb = smem_u32(Ks), vsb = smem_u32(Vs), psb = smem_u32(Ps);

    const __nv_bfloat16* Qg = Q2 + ((size_t)(b * NHc + h) * Tc + q0) * QK_K;
    const __nv_bfloat16* Kg = K2 + ((size_t)(b * NHc + h) * Tc) * QK_K;
    const __nv_bfloat16* Vg = V2 + ((size_t)(b * NHc + h) * 3 * Tc) * HDc;

    // load Q tile (64 x 576 bf16)
#pragma unroll
    for (int i = 0; i < 36; i++) {
        int idx = tid + i * 128, r = idx / 72, seg = idx % 72;
        cp16(qsb + (r * QS_ST + seg * 8) * 2, Qg + (size_t)r * QK_K + seg * 8);
    }
    CP_COMMIT();

    float m0 = -INFINITY, m1 = -INFINITY, l0 = 0.f, l1 = 0.f;
    float oacc[16][4];
#pragma unroll
    for (int i = 0; i < 16; i++)
#pragma unroll
        for (int j = 0; j < 4; j++) oacc[i][j] = 0.f;

    const float inv_scale = 0.0721687836487032f;  // 1/sqrt(192)
    const int arow = wq * 16 + (lane & 15);
    const int acol = (lane >> 4) << 3;
    const int brow_k = ((lane >> 4) << 3) + (lane & 7);       // within 16-row n-group
    const int bcol_k = ((lane >> 3) & 1) << 3;
    const int r0l = lane >> 2;                                 // local fragment row
    const int cgrp = (lane & 3) * 2;

    const int ntiles = blockIdx.x + 1;
    for (int jt = 0; jt < ntiles; jt++) {
        // ---- async loads: K tile, then V tile (V overlaps QK+softmax) ----
        const __nv_bfloat16* Kt = Kg + (size_t)jt * 64 * QK_K;
#pragma unroll
        for (int i = 0; i < 36; i++) {
            int idx = tid + i * 128, r = idx / 72, seg = idx % 72;
            cp16(ksb + (r * QS_ST + seg * 8) * 2, Kt + (size_t)r * QK_K + seg * 8);
        }
        CP_COMMIT();
        const __nv_bfloat16* Vt = Vg + (size_t)jt * 192 * HDc;
#pragma unroll
        for (int i = 0; i < 24; i++) {
            int idx = tid + i * 128, r = idx >> 4, seg = idx & 15;
            cp16(vsb + (r * VS_ST + seg * 8) * 2, Vt + (size_t)r * HDc + seg * 8);
        }
        CP_COMMIT();
        CP_WAIT1();                       // Q (first iter) + K arrived
        __syncthreads();

        // ---- S = Q K^T over k=576 ----
        float sacc[8][4];
#pragma unroll
        for (int i = 0; i < 8; i++)
#pragma unroll
            for (int j = 0; j < 4; j++) sacc[i][j] = 0.f;
#pragma unroll 4
        for (int ks = 0; ks < 36; ks++) {
            uint32_t a[4];
            LDSM4(a, qsb + (arow * QS_ST + ks * 16 + acol) * 2);
#pragma unroll
            for (int nj = 0; nj < 4; nj++) {
                uint32_t r4[4];
                LDSM4(r4, ksb + ((nj * 16 + brow_k) * QS_ST + ks * 16 + bcol_k) * 2);
                MMA16816(sacc[2 * nj],     a, r4[0], r4[1]);
                MMA16816(sacc[2 * nj + 1], a, r4[2], r4[3]);
            }
        }

        // ---- online softmax ----
        const int qrow0 = q0 + wq * 16 + r0l, qrow1 = qrow0 + 8;
        const int s0 = jt * 64;
        const bool diag = (jt == blockIdx.x);
        float mt0 = -INFINITY, mt1 = -INFINITY;
#pragma unroll
        for (int ni = 0; ni < 8; ni++) {
            float v0 = sacc[ni][0] * inv_scale, v1 = sacc[ni][1] * inv_scale;
            float v2 = sacc[ni][2] * inv_scale, v3 = sacc[ni][3] * inv_scale;
            if (diag) {
                int c = s0 + ni * 8 + cgrp;
                if (c > qrow0)     v0 = -INFINITY;
                if (c + 1 > qrow0) v1 = -INFINITY;
                if (c > qrow1)     v2 = -INFINITY;
                if (c + 1 > qrow1) v3 = -INFINITY;
            }
            sacc[ni][0] = v0; sacc[ni][1] = v1; sacc[ni][2] = v2; sacc[ni][3] = v3;
            mt0 = fmaxf(mt0, fmaxf(v0, v1));
            mt1 = fmaxf(mt1, fmaxf(v2, v3));
        }
        mt0 = fmaxf(mt0, __shfl_xor_sync(0xffffffffu, mt0, 1));
        mt0 = fmaxf(mt0, __shfl_xor_sync(0xffffffffu, mt0, 2));
        mt1 = fmaxf(mt1, __shfl_xor_sync(0xffffffffu, mt1, 1));
        mt1 = fmaxf(mt1, __shfl_xor_sync(0xffffffffu, mt1, 2));
        float nm0 = fmaxf(m0, mt0), nm1 = fmaxf(m1, mt1);
        float f0 = __expf(m0 - nm0), f1 = __expf(m1 - nm1);
        float rs0 = 0.f, rs1 = 0.f;
#pragma unroll
        for (int ni = 0; ni < 8; ni++) {
            float p0 = __expf(sacc[ni][0] - nm0);
            float p1 = __expf(sacc[ni][1] - nm0);
            float p2 = __expf(sacc[ni][2] - nm1);
            float p3 = __expf(sacc[ni][3] - nm1);
            rs0 += p0 + p1; rs1 += p2 + p3;
            // split to bf16 triplets (h,h,l)
            __nv_bfloat16 h0 = __float2bfloat16_rn(p0);
            __nv_bfloat16 h1 = __float2bfloat16_rn(p1);
            __nv_bfloat16 h2 = __float2bfloat16_rn(p2);
            __nv_bfloat16 h3 = __float2bfloat16_rn(p3);
            float L0 = p0 - __bfloat162float(h0), L1 = p1 - __bfloat162float(h1);
            float L2 = p2 - __bfloat162float(h2), L3 = p3 - __bfloat162float(h3);
            float F0 = __bfloat162float(h0), F1 = __bfloat162float(h1);
            float F2 = __bfloat162float(h2), F3 = __bfloat162float(h3);
            int cl = ni * 8 + cgrp;
            uint32_t b0 = psb + ((wq * 16 + r0l) * PS_ST + 3 * cl) * 2;
            STS32(b0,     bfpack(F0, F0));
            STS32(b0 + 4, bfpack(L0, F1));
            STS32(b0 + 8, bfpack(F1, L1));
            uint32_t b1 = b0 + 8 * PS_ST * 2;
            STS32(b1,     bfpack(F2, F2));
            STS32(b1 + 4, bfpack(L2, F3));
            STS32(b1 + 8, bfpack(F3, L3));
        }
        rs0 += __shfl_xor_sync(0xffffffffu, rs0, 1);
        rs0 += __shfl_xor_sync(0xffffffffu, rs0, 2);
        rs1 += __shfl_xor_sync(0xffffffffu, rs1, 1);
        rs1 += __shfl_xor_sync(0xffffffffu, rs1, 2);
        l0 = l0 * f0 + rs0; l1 = l1 * f1 + rs1;
        m0 = nm0; m1 = nm1;
#pragma unroll
        for (int ni = 0; ni < 16; ni++) {
            oacc[ni][0] *= f0; oacc[ni][1] *= f0;
            oacc[ni][2] *= f1; oacc[ni][3] *= f1;
        }
        __syncwarp();

        // ---- O += P V over k=192 ----
        CP_WAIT0();
        __syncthreads();
#pragma unroll
        for (int ks = 0; ks < 12; ks++) {
            uint32_t a[4];
            LDSM4(a, psb + (arow * PS_ST + ks * 16 + acol) * 2);
#pragma unroll
            for (int nj = 0; nj < 8; nj++) {
                uint32_t r4[4];
                LDSM4T(r4, vsb + ((ks * 16 + (lane & 15)) * VS_ST + nj * 16 + acol) * 2);
                MMA16816(oacc[2 * nj],     a, r4[0], r4[1]);
                MMA16816(oacc[2 * nj + 1], a, r4[2], r4[3]);
            }
        }
        __syncthreads();   // protect Ks/Vs before next iteration's cp.async
    }

    // ---- epilogue ----
    float il0 = 1.0f / l0, il1 = 1.0f / l1;
    int row0 = q0 + wq * 16 + r0l, row1 = row0 + 8;
#pragma unroll
    for (int ni = 0; ni < 16; ni++) {
        int col = h * HDc + ni * 8 + cgrp;
        *(float2*)(og + ((size_t)b * Tc + row0) * Dc + col) =
            make_float2(oacc[ni][0] * il0, oacc[ni][1] * il0);
        *(float2*)(og + ((size_t)b * Tc + row1) * Dc + col) =
            make_float2(oacc[ni][2] * il1, oacc[ni][3] * il1);
    }
}

// ---------------- launch ---------------------------------------------------------
extern "C" void kernel_launch(void* const* d_in, const int* in_sizes, int n_in,
                              void* d_out, int out_size) {
    const float* x    = (const float*)d_in[0];
    const float* Wkv  = (const float*)d_in[1];
    const float* Wkup = (const float*)d_in[2];
    const float* Wvup = (const float*)d_in[3];
    const float* Wq   = (const float*)d_in[4];
    const float* Wqr  = (const float*)d_in[5];
    const float* Wkr  = (const float*)d_in[6];
    const float* Wo   = (const float*)d_in[7];
    float* out      = (float*)d_out;
    float* outEntry = out + (size_t)BT * Dc;

    float *ckv, *kr, *qr, *q, *k, *v, *att;
    __nv_bfloat16 *x2, *ckv2, *att2, *wkv, *wq, *wqr, *wkr, *wkup, *wvup, *wo, *Q2, *K2, *V2;
    cudaGetSymbolAddress((void**)&ckv,  g_ckv);
    cudaGetSymbolAddress((void**)&kr,   g_kr);
    cudaGetSymbolAddress((void**)&qr,   g_qr);
    cudaGetSymbolAddress((void**)&q,    g_q);
    cudaGetSymbolAddress((void**)&k,    g_k);
    cudaGetSymbolAddress((void**)&v,    g_v);
    cudaGetSymbolAddress((void**)&att,  g_att);
    cudaGetSymbolAddress((void**)&x2,   g_x2);
    cudaGetSymbolAddress((void**)&ckv2, g_ckv2);
    cudaGetSymbolAddress((void**)&att2, g_att2);
    cudaGetSymbolAddress((void**)&wkv,  w_kv);
    cudaGetSymbolAddress((void**)&wq,   w_q);
    cudaGetSymbolAddress((void**)&wqr,  w_qr);
    cudaGetSymbolAddress((void**)&wkr,  w_kr);
    cudaGetSymbolAddress((void**)&wkup, w_kup);
    cudaGetSymbolAddress((void**)&wvup, w_vup);
    cudaGetSymbolAddress((void**)&wo,   w_o);
    cudaGetSymbolAddress((void**)&Q2,   g_Q2);
    cudaGetSymbolAddress((void**)&K2,   g_K2);
    cudaGetSymbolAddress((void**)&V2,   g_V2);

    const int SM128 = (2 * 128 + 2 * 128) * 72 * 2;   // 73728
    const int SM64  = (2 * 128 + 2 * 64)  * 72 * 2;   // 55296
    cudaFuncSetAttribute(gemm_mma<128>, cudaFuncAttributeMaxDynamicSharedMemorySize, SM128);
    cudaFuncSetAttribute(gemm_mma<64>,  cudaFuncAttributeMaxDynamicSharedMemorySize, SM64);
    const int SMATT = (2 * 64 * QS_ST + 192 * VS_ST + 64 * PS_ST) * 2;  // 227328
    cudaFuncSetAttribute(mla_attn_tc, cudaFuncAttributeMaxDynamicSharedMemorySize, SMATT);

    dim3 tb(32, 8);
    tsplit3<<<dim3(DCc / 32, Dc  / 32), tb>>>(Wkv,  wkv,  Dc,  DCc);
    tsplit3<<<dim3(Dc  / 32, Dc  / 32), tb>>>(Wq,   wq,   Dc,  Dc);
    tsplit3<<<dim3(DRc / 32, Dc  / 32), tb>>>(Wqr,  wqr,  Dc,  DRc);
    tsplit3<<<dim3(DRc / 32, DCc / 32), tb>>>(Wkr,  wkr,  DCc, DRc);
    tsplit3<<<dim3(Dc  / 32, DCc / 32), tb>>>(Wkup, wkup, DCc, Dc);
    tsplit3<<<dim3(Dc  / 32, DCc / 32), tb>>>(Wvup, wvup, DCc, Dc);
    tsplit3<<<dim3(Dc  / 32, Dc  / 32), tb>>>(Wo,   wo,   Dc,  Dc);
    split3<<<(BT * Dc + 255) / 256, 256>>>(x, x2, BT * Dc, Dc);

    gemm_mma<128><<<dim3(DCc / 128, BT / 128), 256, SM128>>>(x2, wkv, ckv, BT, DCc, K3D);
    gemm_mma<128><<<dim3(Dc  / 128, BT / 128), 256, SM128>>>(x2, wq,  q,   BT, Dc,  K3D);
    gemm_mma<64> <<<dim3(1,         BT / 128), 256, SM64 >>>(x2, wqr, qr,  BT, DRc, K3D);
    split3<<<(BT * DCc + 255) / 256, 256>>>(ckv, ckv2, BT * DCc, DCc);
    gemm_mma<64> <<<dim3(1,         BT / 128), 256, SM64 >>>(ckv2, wkr,  kr, BT, DRc, K3C);
    gemm_mma<128><<<dim3(Dc  / 128, BT / 128), 256, SM128>>>(ckv2, wkup, k,  BT, Dc,  K3C);
    gemm_mma<128><<<dim3(Dc  / 128, BT / 128), 256, SM128>>>(ckv2, wvup, v,  BT, Dc,  K3C);

    rope_kernel<<<BT, 64>>>(kr, qr);
    write_entry<<<(BT * (DCc + DRc) + 255) / 256, 256>>>(ckv, kr, outEntry);

    // attention: prep split operands, then tensor-core flash
    prep_attn<<<BT * NHc, 192>>>(q, k, v, qr, kr, Q2, K2, V2);
    mla_attn_tc<<<dim3(Tc / 64, NHc, Bc), 128, SMATT>>>(Q2, K2, V2, att);

    split3<<<(BT * Dc + 255) / 256, 256>>>(att, att2, BT * Dc, Dc);
    gemm_mma<128><<<dim3(Dc / 128, BT / 128), 256, SM128>>>(att2, wo, out, BT, Dc, K3D);
}

// round 10
// speedup vs baseline: 2.9025x; 1.0917x over previous
#include <cuda_runtime.h>
#include <cuda_bf16.h>
#include <math.h>
#include <cstdint>

#define Bc  2
#define Tc  2048
#define Dc  2048
#define DCc 512
#define DRc 64
#define NHc 16
#define HDc 128
#define BT  (Bc*Tc)
#define K3D (3*Dc)    /* 6144 */
#define K3C (3*DCc)   /* 1536 */
#define AQK 192
#define QK_K 576      /* 3*192 */
// concatenated GEMM widths (padded to 128)
#define N1   2688     /* ckv(512) | q(2048) | qr(64) | pad(64) */
#define N2   4224     /* k(2048) | v(2048) | kr(64) | pad(64) */
#define C1_Q    512
#define C1_QR   2560
#define C2_V    2048
#define C2_KR   4096

// ---------------- scratch (static device globals; zero-initialized) -------------
__device__ __nv_bfloat16 g_x2  [(size_t)BT*K3D];
__device__ __nv_bfloat16 g_ckv2[(size_t)BT*K3C];
__device__ float g_C1[(size_t)BT*N1];
__device__ float g_C2[(size_t)BT*N2];
__device__ float g_att[(size_t)BT*Dc];
__device__ __nv_bfloat16 g_att2[(size_t)BT*K3D];
__device__ __nv_bfloat16 w_cat1[(size_t)N1*K3D];   // padding rows stay zero
__device__ __nv_bfloat16 w_cat2[(size_t)N2*K3C];
__device__ __nv_bfloat16 w_o   [(size_t)Dc *K3D];
__device__ __nv_bfloat16 g_Q2[(size_t)Bc*NHc*Tc*QK_K];
__device__ __nv_bfloat16 g_K2[(size_t)Bc*NHc*Tc*QK_K];
__device__ __nv_bfloat16 g_V2[(size_t)Bc*NHc*3*Tc*HDc];

// ---------------- helpers -------------------------------------------------------
__device__ __forceinline__ uint32_t smem_u32(const void* p) {
    uint32_t a;
    asm("{ .reg .u64 t; cvta.to.shared.u64 t, %1; cvt.u32.u64 %0, t; }" : "=r"(a) : "l"(p));
    return a;
}
__device__ __forceinline__ void cp16(uint32_t dst, const void* src) {
    asm volatile("cp.async.cg.shared.global [%0], [%1], 16;" :: "r"(dst), "l"(src));
}
#define CP_COMMIT() asm volatile("cp.async.commit_group;" ::: "memory")
#define CP_WAIT0()  asm volatile("cp.async.wait_group 0;" ::: "memory")
#define CP_WAIT1()  asm volatile("cp.async.wait_group 1;" ::: "memory")
#define LDSM4(r, a) \
    asm volatile("ldmatrix.sync.aligned.m8n8.x4.shared.b16 {%0,%1,%2,%3}, [%4];" \
        : "=r"((r)[0]), "=r"((r)[1]), "=r"((r)[2]), "=r"((r)[3]) : "r"(a))
#define LDSM4T(r, a) \
    asm volatile("ldmatrix.sync.aligned.m8n8.x4.trans.shared.b16 {%0,%1,%2,%3}, [%4];" \
        : "=r"((r)[0]), "=r"((r)[1]), "=r"((r)[2]), "=r"((r)[3]) : "r"(a))
#define MMA16816(d, a, b0, b1) \
    asm volatile("mma.sync.aligned.m16n8k16.row.col.f32.bf16.bf16.f32 " \
        "{%0,%1,%2,%3}, {%4,%5,%6,%7}, {%8,%9}, {%0,%1,%2,%3};" \
        : "+f"((d)[0]), "+f"((d)[1]), "+f"((d)[2]), "+f"((d)[3]) \
        : "r"((a)[0]), "r"((a)[1]), "r"((a)[2]), "r"((a)[3]), "r"(b0), "r"(b1))
#define STS32(a, v) asm volatile("st.shared.b32 [%0], %1;" :: "r"(a), "r"(v) : "memory")
__device__ __forceinline__ uint32_t bfpack(float a, float b) {
    __nv_bfloat162 t = __floats2bfloat162_rn(a, b);
    return *(uint32_t*)&t;
}

// ---------------- conversion kernels --------------------------------------------
// A-side split with source row stride: out[m][3k]=(h,h,l)
__global__ void split3s(const float* __restrict__ A, int srcStride,
                        __nv_bfloat16* __restrict__ O, int total, int K) {
    int idx = blockIdx.x * blockDim.x + threadIdx.x;
    if (idx >= total) return;
    int k = idx % K, m = idx / K;
    float v = A[(size_t)m * srcStride + k];
    __nv_bfloat16 h = __float2bfloat16_rn(v);
    __nv_bfloat16 l = __float2bfloat16_rn(v - __bfloat162float(h));
    size_t o = (size_t)m * (3 * K) + 3 * k;
    O[o] = h; O[o + 1] = h; O[o + 2] = l;
}
// B-side transpose+split: W[K,N] -> O[N][3K], (h,l,h)
__global__ void tsplit3(const float* __restrict__ W, __nv_bfloat16* __restrict__ O, int K, int N) {
    __shared__ float t[32][33];
    int n0 = blockIdx.x * 32, k0 = blockIdx.y * 32;
    int tx = threadIdx.x, ty = threadIdx.y;
    for (int i = ty; i < 32; i += 8)
        t[i][tx] = W[(size_t)(k0 + i) * N + n0 + tx];
    __syncthreads();
    for (int i = ty; i < 32; i += 8) {
        int n = n0 + i, k = k0 + tx;
        float v = t[tx][i];
        __nv_bfloat16 h = __float2bfloat16_rn(v);
        __nv_bfloat16 l = __float2bfloat16_rn(v - __bfloat162float(h));
        size_t o = (size_t)n * (3 * K) + 3 * k;
        O[o] = h; O[o + 1] = l; O[o + 2] = h;
    }
}

// ---------------- mma.sync GEMM, 3-stage cp.async pipeline -----------------------
#define GNST 3
__global__ void __launch_bounds__(256) gemm_mma(
    const __nv_bfloat16* __restrict__ A, const __nv_bfloat16* __restrict__ B,
    float* __restrict__ C, int M, int N, int K)
{
    constexpr int BM = 128, BN = 128, BK = 64;
    constexpr int ST = 72;
    extern __shared__ __nv_bfloat16 smem[];
    __nv_bfloat16* As = smem;                       // [GNST][BM][ST]
    __nv_bfloat16* Bs = smem + GNST * BM * ST;      // [GNST][BN][ST]

    const int tid = threadIdx.x, lane = tid & 31, wid = tid >> 5;
    const int wm = wid >> 2, wn = wid & 3;
    const int bm = blockIdx.y * BM, bn = blockIdx.x * BN;

    float acc[4][4][4];
#pragma unroll
    for (int i = 0; i < 4; i++)
#pragma unroll
        for (int j = 0; j < 4; j++)
#pragma unroll
            for (int r = 0; r < 4; r++) acc[i][j][r] = 0.f;

    const uint32_t asb = smem_u32(As), bsb = smem_u32(Bs);

    auto loadStage = [&](int it, int buf) {
        const __nv_bfloat16* Ag = A + (size_t)bm * K + it * BK;
        uint32_t ad = asb + buf * BM * ST * 2;
#pragma unroll
        for (int i = 0; i < 4; i++) {
            int c = tid + i * 256, r = c >> 3, cc = c & 7;
            cp16(ad + (r * ST + cc * 8) * 2, Ag + (size_t)r * K + cc * 8);
        }
        const __nv_bfloat16* Bg = B + (size_t)bn * K + it * BK;
        uint32_t bd = bsb + buf * BN * ST * 2;
#pragma unroll
        for (int i = 0; i < 4; i++) {
            int c = tid + i * 256, r = c >> 3, cc = c & 7;
            cp16(bd + (r * ST + cc * 8) * 2, Bg + (size_t)r * K + cc * 8);
        }
        CP_COMMIT();
    };

    const int nIter = K / BK;
    loadStage(0, 0);
    loadStage(1, 1);
    for (int it = 0; it < nIter; it++) {
        const int buf = it % GNST;
        if (it + 1 < nIter) CP_WAIT1(); else CP_WAIT0();
        __syncthreads();
        if (it + 2 < nIter) loadStage(it + 2, (it + 2) % GNST);

        const uint32_t ab = asb + buf * BM * ST * 2;
        const uint32_t bb = bsb + buf * BN * ST * 2;
#pragma unroll
        for (int ks = 0; ks < BK / 16; ks++) {
            uint32_t a[4][4];
#pragma unroll
            for (int mi = 0; mi < 4; mi++) {
                int row = wm * 64 + mi * 16 + (lane & 15);
                LDSM4(a[mi], ab + (row * ST + ks * 16 + ((lane >> 4) << 3)) * 2);
            }
            uint32_t b[4][2];
#pragma unroll
            for (int nj = 0; nj < 2; nj++) {
                int row = wn * 32 + nj * 16 + ((lane >> 4) << 3) + (lane & 7);
                uint32_t r4[4];
                LDSM4(r4, bb + (row * ST + ks * 16 + (((lane >> 3) & 1) << 3)) * 2);
                b[nj * 2][0] = r4[0]; b[nj * 2][1] = r4[1];
                b[nj * 2 + 1][0] = r4[2]; b[nj * 2 + 1][1] = r4[3];
            }
#pragma unroll
            for (int mi = 0; mi < 4; mi++)
#pragma unroll
                for (int ni = 0; ni < 4; ni++)
                    MMA16816(acc[mi][ni], a[mi], b[ni][0], b[ni][1]);
        }
    }

#pragma unroll
    for (int mi = 0; mi < 4; mi++) {
        int row0 = bm + wm * 64 + mi * 16 + (lane >> 2);
#pragma unroll
        for (int ni = 0; ni < 4; ni++) {
            int col = bn + wn * 32 + ni * 8 + (lane & 3) * 2;
            *(float2*)(C + (size_t)row0 * N + col)       = make_float2(acc[mi][ni][0], acc[mi][ni][1]);
            *(float2*)(C + (size_t)(row0 + 8) * N + col) = make_float2(acc[mi][ni][2], acc[mi][ni][3]);
        }
    }
}

// ---------------- RoPE (strided, in-place on kr/qr regions) ----------------------
__global__ void rope_kernel(float* __restrict__ krBase, int krStride,
                            float* __restrict__ qrBase, int qrStride) {
    int bt = blockIdx.x;
    int t  = bt % Tc;
    int i  = threadIdx.x;
    float* row = (i < 32) ? (krBase + (size_t)bt * krStride)
                          : (qrBase + (size_t)bt * qrStride);
    int ii = i & 31;
    double inv = exp(-log(10000.0) * (2.0 * ii) / 64.0);
    double ang = (double)t * inv;
    float cs = (float)cos(ang), sn = (float)sin(ang);
    float x1 = row[ii], x2 = row[ii + 32];
    row[ii]      = x1 * cs - x2 * sn;
    row[ii + 32] = x2 * cs + x1 * sn;
}

// ---------------- entry = concat(ckv, rope(kr)) ----------------------------------
__global__ void write_entry(const float* __restrict__ C1, const float* __restrict__ C2,
                            float* __restrict__ e) {
    int idx = blockIdx.x * blockDim.x + threadIdx.x;
    if (idx >= BT * (DCc + DRc)) return;
    int c  = idx % (DCc + DRc);
    int bt = idx / (DCc + DRc);
    e[idx] = (c < DCc) ? C1[(size_t)bt * N1 + c]
                       : C2[(size_t)bt * N2 + C2_KR + (c - DCc)];
}

// ---------------- attention prep: per-head split operands ------------------------
__global__ void prep_attn(const float* __restrict__ C1, const float* __restrict__ C2,
                          __nv_bfloat16* __restrict__ Q2, __nv_bfloat16* __restrict__ K2,
                          __nv_bfloat16* __restrict__ V2) {
    int bid = blockIdx.x;               // bt*NH + h
    int bt = bid / NHc, h = bid % NHc;
    int b = bt / Tc, t = bt % Tc;
    int c = threadIdx.x;                // 0..191
    size_t rowQK = ((size_t)(b * NHc + h) * Tc + t) * QK_K;
    {
        float qv = (c < HDc) ? C1[(size_t)bt * N1 + C1_Q + h * HDc + c]
                             : C1[(size_t)bt * N1 + C1_QR + (c - HDc)];
        __nv_bfloat16 hh = __float2bfloat16_rn(qv);
        __nv_bfloat16 ll = __float2bfloat16_rn(qv - __bfloat162float(hh));
        Q2[rowQK + 3 * c] = hh; Q2[rowQK + 3 * c + 1] = hh; Q2[rowQK + 3 * c + 2] = ll;
        float kv = (c < HDc) ? C2[(size_t)bt * N2 + h * HDc + c]
                             : C2[(size_t)bt * N2 + C2_KR + (c - HDc)];
        hh = __float2bfloat16_rn(kv);
        ll = __float2bfloat16_rn(kv - __bfloat162float(hh));
        K2[rowQK + 3 * c] = hh; K2[rowQK + 3 * c + 1] = ll; K2[rowQK + 3 * c + 2] = hh;
    }
    if (c < HDc) {
        float vv = C2[(size_t)bt * N2 + C2_V + h * HDc + c];
        __nv_bfloat16 hh = __float2bfloat16_rn(vv);
        __nv_bfloat16 ll = __float2bfloat16_rn(vv - __bfloat162float(hh));
        size_t base = ((size_t)(b * NHc + h) * 3 * Tc + 3 * t) * HDc + c;
        V2[base] = hh; V2[base + HDc] = ll; V2[base + 2 * HDc] = hh;
    }
}

// ---------------- tensor-core flash attention (validated round 9) ----------------
#define QS_ST 584
#define VS_ST 136
#define PS_ST 200

__global__ void __launch_bounds__(128) mla_attn_tc(
    const __nv_bfloat16* __restrict__ Q2, const __nv_bfloat16* __restrict__ K2,
    const __nv_bfloat16* __restrict__ V2, float* __restrict__ og)
{
    extern __shared__ __nv_bfloat16 sm2[];
    __nv_bfloat16* Qs = sm2;
    __nv_bfloat16* Ks = Qs + 64 * QS_ST;
    __nv_bfloat16* Vs = Ks + 64 * QS_ST;
    __nv_bfloat16* Ps = Vs + 192 * VS_ST;

    const int tid = threadIdx.x, lane = tid & 31, wq = tid >> 5;
    const int q0 = blockIdx.x * 64, h = blockIdx.y, b = blockIdx.z;
    const uint32_t qsb = smem_u32(Qs), ksb = smem_u32(Ks), vsb = smem_u32(Vs), psb = smem_u32(Ps);

    const __nv_bfloat16* Qg = Q2 + ((size_t)(b * NHc + h) * Tc + q0) * QK_K;
    const __nv_bfloat16* Kg = K2 + ((size_t)(b * NHc + h) * Tc) * QK_K;
    const __nv_bfloat16* Vg = V2 + ((size_t)(b * NHc + h) * 3 * Tc) * HDc;

#pragma unroll
    for (int i = 0; i < 36; i++) {
        int idx = tid + i * 128, r = idx / 72, seg = idx % 72;
        cp16(qsb + (r * QS_ST + seg * 8) * 2, Qg + (size_t)r * QK_K + seg * 8);
    }
    CP_COMMIT();

    float m0 = -INFINITY, m1 = -INFINITY, l0 = 0.f, l1 = 0.f;
    float oacc[16][4];
#pragma unroll
    for (int i = 0; i < 16; i++)
#pragma unroll
        for (int j = 0; j < 4; j++) oacc[i][j] = 0.f;

    const float inv_scale = 0.0721687836487032f;
    const int arow = wq * 16 + (lane & 15);
    const int acol = (lane >> 4) << 3;
    const int brow_k = ((lane >> 4) << 3) + (lane & 7);
    const int bcol_k = ((lane >> 3) & 1) << 3;
    const int r0l = lane >> 2;
    const int cgrp = (lane & 3) * 2;

    const int ntiles = blockIdx.x + 1;
    for (int jt = 0; jt < ntiles; jt++) {
        const __nv_bfloat16* Kt = Kg + (size_t)jt * 64 * QK_K;
#pragma unroll
        for (int i = 0; i < 36; i++) {
            int idx = tid + i * 128, r = idx / 72, seg = idx % 72;
            cp16(ksb + (r * QS_ST + seg * 8) * 2, Kt + (size_t)r * QK_K + seg * 8);
        }
        CP_COMMIT();
        const __nv_bfloat16* Vt = Vg + (size_t)jt * 192 * HDc;
#pragma unroll
        for (int i = 0; i < 24; i++) {
            int idx = tid + i * 128, r = idx >> 4, seg = idx & 15;
            cp16(vsb + (r * VS_ST + seg * 8) * 2, Vt + (size_t)r * HDc + seg * 8);
        }
        CP_COMMIT();
        CP_WAIT1();
        __syncthreads();

        float sacc[8][4];
#pragma unroll
        for (int i = 0; i < 8; i++)
#pragma unroll
            for (int j = 0; j < 4; j++) sacc[i][j] = 0.f;
#pragma unroll 4
        for (int ks = 0; ks < 36; ks++) {
            uint32_t a[4];
            LDSM4(a, qsb + (arow * QS_ST + ks * 16 + acol) * 2);
#pragma unroll
            for (int nj = 0; nj < 4; nj++) {
                uint32_t r4[4];
                LDSM4(r4, ksb + ((nj * 16 + brow_k) * QS_ST + ks * 16 + bcol_k) * 2);
                MMA16816(sacc[2 * nj],     a, r4[0], r4[1]);
                MMA16816(sacc[2 * nj + 1], a, r4[2], r4[3]);
            }
        }

        const int qrow0 = q0 + wq * 16 + r0l, qrow1 = qrow0 + 8;
        const int s0 = jt * 64;
        const bool diag = (jt == blockIdx.x);
        float mt0 = -INFINITY, mt1 = -INFINITY;
#pragma unroll
        for (int ni = 0; ni < 8; ni++) {
            float v0 = sacc[ni][0] * inv_scale, v1 = sacc[ni][1] * inv_scale;
            float v2 = sacc[ni][2] * inv_scale, v3 = sacc[ni][3] * inv_scale;
            if (diag) {
                int c = s0 + ni * 8 + cgrp;
                if (c > qrow0)     v0 = -INFINITY;
                if (c + 1 > qrow0) v1 = -INFINITY;
                if (c > qrow1)     v2 = -INFINITY;
                if (c + 1 > qrow1) v3 = -INFINITY;
            }
            sacc[ni][0] = v0; sacc[ni][1] = v1; sacc[ni][2] = v2; sacc[ni][3] = v3;
            mt0 = fmaxf(mt0, fmaxf(v0, v1));
            mt1 = fmaxf(mt1, fmaxf(v2, v3));
        }
        mt0 = fmaxf(mt0, __shfl_xor_sync(0xffffffffu, mt0, 1));
        mt0 = fmaxf(mt0, __shfl_xor_sync(0xffffffffu, mt0, 2));
        mt1 = fmaxf(mt1, __shfl_xor_sync(0xffffffffu, mt1, 1));
        mt1 = fmaxf(mt1, __shfl_xor_sync(0xffffffffu, mt1, 2));
        float nm0 = fmaxf(m0, mt0), nm1 = fmaxf(m1, mt1);
        float f0 = __expf(m0 - nm0), f1 = __expf(m1 - nm1);
        float rs0 = 0.f, rs1 = 0.f;
#pragma unroll
        for (int ni = 0; ni < 8; ni++) {
            float p0 = __expf(sacc[ni][0] - nm0);
            float p1 = __expf(sacc[ni][1] - nm0);
            float p2 = __expf(sacc[ni][2] - nm1);
            float p3 = __expf(sacc[ni][3] - nm1);
            rs0 += p0 + p1; rs1 += p2 + p3;
            __nv_bfloat16 h0 = __float2bfloat16_rn(p0);
            __nv_bfloat16 h1 = __float2bfloat16_rn(p1);
            __nv_bfloat16 h2 = __float2bfloat16_rn(p2);
            __nv_bfloat16 h3 = __float2bfloat16_rn(p3);
            float L0 = p0 - __bfloat162float(h0), L1 = p1 - __bfloat162float(h1);
            float L2 = p2 - __bfloat162float(h2), L3 = p3 - __bfloat162float(h3);
            float F0 = __bfloat162float(h0), F1 = __bfloat162float(h1);
            float F2 = __bfloat162float(h2), F3 = __bfloat162float(h3);
            int cl = ni * 8 + cgrp;
            uint32_t b0 = psb + ((wq * 16 + r0l) * PS_ST + 3 * cl) * 2;
            STS32(b0,     bfpack(F0, F0));
            STS32(b0 + 4, bfpack(L0, F1));
            STS32(b0 + 8, bfpack(F1, L1));
            uint32_t b1 = b0 + 8 * PS_ST * 2;
            STS32(b1,     bfpack(F2, F2));
            STS32(b1 + 4, bfpack(L2, F3));
            STS32(b1 + 8, bfpack(F3, L3));
        }
        rs0 += __shfl_xor_sync(0xffffffffu, rs0, 1);
        rs0 += __shfl_xor_sync(0xffffffffu, rs0, 2);
        rs1 += __shfl_xor_sync(0xffffffffu, rs1, 1);
        rs1 += __shfl_xor_sync(0xffffffffu, rs1, 2);
        l0 = l0 * f0 + rs0; l1 = l1 * f1 + rs1;
        m0 = nm0; m1 = nm1;
#pragma unroll
        for (int ni = 0; ni < 16; ni++) {
            oacc[ni][0] *= f0; oacc[ni][1] *= f0;
            oacc[ni][2] *= f1; oacc[ni][3] *= f1;
        }
        __syncwarp();

        CP_WAIT0();
        __syncthreads();
#pragma unroll
        for (int ks = 0; ks < 12; ks++) {
            uint32_t a[4];
            LDSM4(a, psb + (arow * PS_ST + ks * 16 + acol) * 2);
#pragma unroll
            for (int nj = 0; nj < 8; nj++) {
                uint32_t r4[4];
                LDSM4T(r4, vsb + ((ks * 16 + (lane & 15)) * VS_ST + nj * 16 + acol) * 2);
                MMA16816(oacc[2 * nj],     a, r4[0], r4[1]);
                MMA16816(oacc[2 * nj + 1], a, r4[2], r4[3]);
            }
        }
        __syncthreads();
    }

    float il0 = 1.0f / l0, il1 = 1.0f / l1;
    int row0 = q0 + wq * 16 + r0l, row1 = row0 + 8;
#pragma unroll
    for (int ni = 0; ni < 16; ni++) {
        int col = h * HDc + ni * 8 + cgrp;
        *(float2*)(og + ((size_t)b * Tc + row0) * Dc + col) =
            make_float2(oacc[ni][0] * il0, oacc[ni][1] * il0);
        *(float2*)(og + ((size_t)b * Tc + row1) * Dc + col) =
            make_float2(oacc[ni][2] * il1, oacc[ni][3] * il1);
    }
}

// ---------------- launch ---------------------------------------------------------
extern "C" void kernel_launch(void* const* d_in, const int* in_sizes, int n_in,
                              void* d_out, int out_size) {
    const float* x    = (const float*)d_in[0];
    const float* Wkv  = (const float*)d_in[1];
    const float* Wkup = (const float*)d_in[2];
    const float* Wvup = (const float*)d_in[3];
    const float* Wq   = (const float*)d_in[4];
    const float* Wqr  = (const float*)d_in[5];
    const float* Wkr  = (const float*)d_in[6];
    const float* Wo   = (const float*)d_in[7];
    float* out      = (float*)d_out;
    float* outEntry = out + (size_t)BT * Dc;

    float *C1, *C2, *att;
    __nv_bfloat16 *x2, *ckv2, *att2, *wc1, *wc2, *wo, *Q2, *K2, *V2;
    cudaGetSymbolAddress((void**)&C1,   g_C1);
    cudaGetSymbolAddress((void**)&C2,   g_C2);
    cudaGetSymbolAddress((void**)&att,  g_att);
    cudaGetSymbolAddress((void**)&x2,   g_x2);
    cudaGetSymbolAddress((void**)&ckv2, g_ckv2);
    cudaGetSymbolAddress((void**)&att2, g_att2);
    cudaGetSymbolAddress((void**)&wc1,  w_cat1);
    cudaGetSymbolAddress((void**)&wc2,  w_cat2);
    cudaGetSymbolAddress((void**)&wo,   w_o);
    cudaGetSymbolAddress((void**)&Q2,   g_Q2);
    cudaGetSymbolAddress((void**)&K2,   g_K2);
    cudaGetSymbolAddress((void**)&V2,   g_V2);

    const int SMG = GNST * (128 + 128) * 72 * 2;   // 110592
    cudaFuncSetAttribute(gemm_mma, cudaFuncAttributeMaxDynamicSharedMemorySize, SMG);
    const int SMATT = (2 * 64 * QS_ST + 192 * VS_ST + 64 * PS_ST) * 2;  // 227328
    cudaFuncSetAttribute(mla_attn_tc, cudaFuncAttributeMaxDynamicSharedMemorySize, SMATT);

    dim3 tb(32, 8);
    // weight transpose+split into concatenated buffers (padding rows remain zero)
    tsplit3<<<dim3(DCc / 32, Dc  / 32), tb>>>(Wkv,  wc1,                        Dc,  DCc);
    tsplit3<<<dim3(Dc  / 32, Dc  / 32), tb>>>(Wq,   wc1 + (size_t)C1_Q  * K3D, Dc,  Dc);
    tsplit3<<<dim3(DRc / 32, Dc  / 32), tb>>>(Wqr,  wc1 + (size_t)C1_QR * K3D, Dc,  DRc);
    tsplit3<<<dim3(Dc  / 32, DCc / 32), tb>>>(Wkup, wc2,                        DCc, Dc);
    tsplit3<<<dim3(Dc  / 32, DCc / 32), tb>>>(Wvup, wc2 + (size_t)C2_V  * K3C, DCc, Dc);
    tsplit3<<<dim3(DRc / 32, DCc / 32), tb>>>(Wkr,  wc2 + (size_t)C2_KR * K3C, DCc, DRc);
    tsplit3<<<dim3(Dc  / 32, Dc  / 32), tb>>>(Wo,   wo,                         Dc,  Dc);
    // activation split
    split3s<<<(BT * Dc + 255) / 256, 256>>>(x, Dc, x2, BT * Dc, Dc);

    // GEMM1: C1 = x2 @ [Wkv|Wq|Wqr]
    gemm_mma<<<dim3(N1 / 128, BT / 128), 256, SMG>>>(x2, wc1, C1, BT, N1, K3D);
    // split ckv (cols 0..511 of C1) -> ckv2
    split3s<<<(BT * DCc + 255) / 256, 256>>>(C1, N1, ckv2, BT * DCc, DCc);
    // GEMM2: C2 = ckv2 @ [Wkup|Wvup|Wkr]
    gemm_mma<<<dim3(N2 / 128, BT / 128), 256, SMG>>>(ckv2, wc2, C2, BT, N2, K3C);

    // rope on kr (C2) and qr (C1), then entry output
    rope_kernel<<<BT, 64>>>(C2 + C2_KR, N2, C1 + C1_QR, N1);
    write_entry<<<(BT * (DCc + DRc) + 255) / 256, 256>>>(C1, C2, outEntry);

    // attention
    prep_attn<<<BT * NHc, 192>>>(C1, C2, Q2, K2, V2);
    mla_attn_tc<<<dim3(Tc / 64, NHc, Bc), 128, SMATT>>>(Q2, K2, V2, att);

    // output projection
    split3s<<<(BT * Dc + 255) / 256, 256>>>(att, Dc, att2, BT * Dc, Dc);
    gemm_mma<<<dim3(Dc / 128, BT / 128), 256, SMG>>>(att2, wo, out, BT, Dc, K3D);
}

// round 12
// speedup vs baseline: 3.5051x; 1.2076x over previous
#include <cuda_runtime.h>
#include <cuda_bf16.h>
#include <cuda_fp16.h>
#include <math.h>
#include <cstdint>

#define Bc  2
#define Tc  2048
#define Dc  2048
#define DCc 512
#define DRc 64
#define NHc 16
#define HDc 128
#define BT  (Bc*Tc)
#define K2D (2*Dc)    /* 4096 : fp16 2-term */
#define K2C (2*DCc)   /* 1024 */
#define AQK 192
#define QK_K 576      /* 3*192 (attention keeps bf16 3-term) */
// concatenated GEMM widths (padded to 128)
#define N1   2688     /* ckv(512) | q(2048) | qr(64) | pad(64) */
#define N2   4224     /* k(2048) | v(2048) | kr(64) | pad(64) */
#define C1_Q    512
#define C1_QR   2560
#define C2_V    2048
#define C2_KR   4096

// ---------------- scratch (static device globals; zero-initialized) -------------
__device__ __half g_x2  [(size_t)BT*K2D];
__device__ __half g_ckv2[(size_t)BT*K2C];
__device__ float g_C1[(size_t)BT*N1];
__device__ float g_C2[(size_t)BT*N2];
__device__ float g_att[(size_t)BT*Dc];
__device__ __half g_att2[(size_t)BT*K2D];
__device__ __half w_cat1[(size_t)N1*K2D];   // padding rows stay zero
__device__ __half w_cat2[(size_t)N2*K2C];
__device__ __half w_o   [(size_t)Dc *K2D];
__device__ __nv_bfloat16 g_Q2[(size_t)Bc*NHc*Tc*QK_K];
__device__ __nv_bfloat16 g_K2[(size_t)Bc*NHc*Tc*QK_K];
__device__ __nv_bfloat16 g_V2[(size_t)Bc*NHc*3*Tc*HDc];

// ---------------- helpers -------------------------------------------------------
__device__ __forceinline__ uint32_t smem_u32(const void* p) {
    uint32_t a;
    asm("{ .reg .u64 t; cvta.to.shared.u64 t, %1; cvt.u32.u64 %0, t; }" : "=r"(a) : "l"(p));
    return a;
}
__device__ __forceinline__ void cp16(uint32_t dst, const void* src) {
    asm volatile("cp.async.cg.shared.global [%0], [%1], 16;" :: "r"(dst), "l"(src));
}
#define CP_COMMIT() asm volatile("cp.async.commit_group;" ::: "memory")
#define CP_WAIT0()  asm volatile("cp.async.wait_group 0;" ::: "memory")
#define CP_WAIT1()  asm volatile("cp.async.wait_group 1;" ::: "memory")
#define LDSM4(r, a) \
    asm volatile("ldmatrix.sync.aligned.m8n8.x4.shared.b16 {%0,%1,%2,%3}, [%4];" \
        : "=r"((r)[0]), "=r"((r)[1]), "=r"((r)[2]), "=r"((r)[3]) : "r"(a))
#define LDSM4T(r, a) \
    asm volatile("ldmatrix.sync.aligned.m8n8.x4.trans.shared.b16 {%0,%1,%2,%3}, [%4];" \
        : "=r"((r)[0]), "=r"((r)[1]), "=r"((r)[2]), "=r"((r)[3]) : "r"(a))
#define MMA16816BF(d, a, b0, b1) \
    asm volatile("mma.sync.aligned.m16n8k16.row.col.f32.bf16.bf16.f32 " \
        "{%0,%1,%2,%3}, {%4,%5,%6,%7}, {%8,%9}, {%0,%1,%2,%3};" \
        : "+f"((d)[0]), "+f"((d)[1]), "+f"((d)[2]), "+f"((d)[3]) \
        : "r"((a)[0]), "r"((a)[1]), "r"((a)[2]), "r"((a)[3]), "r"(b0), "r"(b1))
#define MMA16816F16(d, a, b0, b1) \
    asm volatile("mma.sync.aligned.m16n8k16.row.col.f32.f16.f16.f32 " \
        "{%0,%1,%2,%3}, {%4,%5,%6,%7}, {%8,%9}, {%0,%1,%2,%3};" \
        : "+f"((d)[0]), "+f"((d)[1]), "+f"((d)[2]), "+f"((d)[3]) \
        : "r"((a)[0]), "r"((a)[1]), "r"((a)[2]), "r"((a)[3]), "r"(b0), "r"(b1))
#define STS32(a, v) asm volatile("st.shared.b32 [%0], %1;" :: "r"(a), "r"(v) : "memory")
__device__ __forceinline__ uint32_t bfpack(float a, float b) {
    __nv_bfloat162 t = __floats2bfloat162_rn(a, b);
    return *(uint32_t*)&t;
}

// ---------------- conversion kernels --------------------------------------------
// A-side fp16 2-term split (strided src): out[m][2k]=(ah, al), ah+al ≈ a
__global__ void split2s(const float* __restrict__ A, int srcStride,
                        __half* __restrict__ O, int total, int K) {
    int idx = blockIdx.x * blockDim.x + threadIdx.x;
    if (idx >= total) return;
    int k = idx % K, m = idx / K;
    float v = A[(size_t)m * srcStride + k];
    __half h = __float2half_rn(v);
    __half l = __float2half_rn(v - __half2float(h));
    size_t o = (size_t)m * (2 * K) + 2 * k;
    O[o] = h; O[o + 1] = l;
}
// B-side transpose + fp16 hi dup: W[K,N] -> O[N][2K], (bh, bh)
__global__ void tsplit2(const float* __restrict__ W, __half* __restrict__ O, int K, int N) {
    __shared__ float t[32][33];
    int n0 = blockIdx.x * 32, k0 = blockIdx.y * 32;
    int tx = threadIdx.x, ty = threadIdx.y;
    for (int i = ty; i < 32; i += 8)
        t[i][tx] = W[(size_t)(k0 + i) * N + n0 + tx];
    __syncthreads();
    for (int i = ty; i < 32; i += 8) {
        int n = n0 + i, k = k0 + tx;
        __half h = __float2half_rn(t[tx][i]);
        size_t o = (size_t)n * (2 * K) + 2 * k;
        O[o] = h; O[o + 1] = h;
    }
}

// ---------------- mma.sync fp16 GEMM, 3-stage cp.async pipeline ------------------
#define GNST 3
__global__ void __launch_bounds__(256) gemm_mma(
    const __half* __restrict__ A, const __half* __restrict__ B,
    float* __restrict__ C, int M, int N, int K)
{
    constexpr int BM = 128, BN = 128, BK = 64;
    constexpr int ST = 72;
    extern __shared__ __half smem[];
    __half* As = smem;                       // [GNST][BM][ST]
    __half* Bs = smem + GNST * BM * ST;      // [GNST][BN][ST]

    const int tid = threadIdx.x, lane = tid & 31, wid = tid >> 5;
    const int wm = wid >> 2, wn = wid & 3;
    const int bm = blockIdx.y * BM, bn = blockIdx.x * BN;

    float acc[4][4][4];
#pragma unroll
    for (int i = 0; i < 4; i++)
#pragma unroll
        for (int j = 0; j < 4; j++)
#pragma unroll
            for (int r = 0; r < 4; r++) acc[i][j][r] = 0.f;

    const uint32_t asb = smem_u32(As), bsb = smem_u32(Bs);

    auto loadStage = [&](int it, int buf) {
        const __half* Ag = A + (size_t)bm * K + it * BK;
        uint32_t ad = asb + buf * BM * ST * 2;
#pragma unroll
        for (int i = 0; i < 4; i++) {
            int c = tid + i * 256, r = c >> 3, cc = c & 7;
            cp16(ad + (r * ST + cc * 8) * 2, Ag + (size_t)r * K + cc * 8);
        }
        const __half* Bg = B + (size_t)bn * K + it * BK;
        uint32_t bd = bsb + buf * BN * ST * 2;
#pragma unroll
        for (int i = 0; i < 4; i++) {
            int c = tid + i * 256, r = c >> 3, cc = c & 7;
            cp16(bd + (r * ST + cc * 8) * 2, Bg + (size_t)r * K + cc * 8);
        }
        CP_COMMIT();
    };

    const int nIter = K / BK;
    loadStage(0, 0);
    loadStage(1, 1);
    for (int it = 0; it < nIter; it++) {
        const int buf = it % GNST;
        if (it + 1 < nIter) CP_WAIT1(); else CP_WAIT0();
        __syncthreads();
        if (it + 2 < nIter) loadStage(it + 2, (it + 2) % GNST);

        const uint32_t ab = asb + buf * BM * ST * 2;
        const uint32_t bb = bsb + buf * BN * ST * 2;
#pragma unroll
        for (int ks = 0; ks < BK / 16; ks++) {
            uint32_t a[4][4];
#pragma unroll
            for (int mi = 0; mi < 4; mi++) {
                int row = wm * 64 + mi * 16 + (lane & 15);
                LDSM4(a[mi], ab + (row * ST + ks * 16 + ((lane >> 4) << 3)) * 2);
            }
            uint32_t b[4][2];
#pragma unroll
            for (int nj = 0; nj < 2; nj++) {
                int row = wn * 32 + nj * 16 + ((lane >> 4) << 3) + (lane & 7);
                uint32_t r4[4];
                LDSM4(r4, bb + (row * ST + ks * 16 + (((lane >> 3) & 1) << 3)) * 2);
                b[nj * 2][0] = r4[0]; b[nj * 2][1] = r4[1];
                b[nj * 2 + 1][0] = r4[2]; b[nj * 2 + 1][1] = r4[3];
            }
#pragma unroll
            for (int mi = 0; mi < 4; mi++)
#pragma unroll
                for (int ni = 0; ni < 4; ni++)
                    MMA16816F16(acc[mi][ni], a[mi], b[ni][0], b[ni][1]);
        }
    }

#pragma unroll
    for (int mi = 0; mi < 4; mi++) {
        int row0 = bm + wm * 64 + mi * 16 + (lane >> 2);
#pragma unroll
        for (int ni = 0; ni < 4; ni++) {
            int col = bn + wn * 32 + ni * 8 + (lane & 3) * 2;
            *(float2*)(C + (size_t)row0 * N + col)       = make_float2(acc[mi][ni][0], acc[mi][ni][1]);
            *(float2*)(C + (size_t)(row0 + 8) * N + col) = make_float2(acc[mi][ni][2], acc[mi][ni][3]);
        }
    }
}

// ---------------- RoPE (strided, in-place on kr/qr regions) ----------------------
__global__ void rope_kernel(float* __restrict__ krBase, int krStride,
                            float* __restrict__ qrBase, int qrStride) {
    int bt = blockIdx.x;
    int t  = bt % Tc;
    int i  = threadIdx.x;
    float* row = (i < 32) ? (krBase + (size_t)bt * krStride)
                          : (qrBase + (size_t)bt * qrStride);
    int ii = i & 31;
    double inv = exp(-log(10000.0) * (2.0 * ii) / 64.0);
    double ang = (double)t * inv;
    float cs = (float)cos(ang), sn = (float)sin(ang);
    float x1 = row[ii], x2 = row[ii + 32];
    row[ii]      = x1 * cs - x2 * sn;
    row[ii + 32] = x2 * cs + x1 * sn;
}

// ---------------- entry = concat(ckv, rope(kr)) ----------------------------------
__global__ void write_entry(const float* __restrict__ C1, const float* __restrict__ C2,
                            float* __restrict__ e) {
    int idx = blockIdx.x * blockDim.x + threadIdx.x;
    if (idx >= BT * (DCc + DRc)) return;
    int c  = idx % (DCc + DRc);
    int bt = idx / (DCc + DRc);
    e[idx] = (c < DCc) ? C1[(size_t)bt * N1 + c]
                       : C2[(size_t)bt * N2 + C2_KR + (c - DCc)];
}

// ---------------- attention prep: per-head bf16 3-term operands ------------------
__global__ void prep_attn(const float* __restrict__ C1, const float* __restrict__ C2,
                          __nv_bfloat16* __restrict__ Q2, __nv_bfloat16* __restrict__ K2,
                          __nv_bfloat16* __restrict__ V2) {
    int bid = blockIdx.x;               // bt*NH + h
    int bt = bid / NHc, h = bid % NHc;
    int b = bt / Tc, t = bt % Tc;
    int c = threadIdx.x;                // 0..191
    size_t rowQK = ((size_t)(b * NHc + h) * Tc + t) * QK_K;
    {
        float qv = (c < HDc) ? C1[(size_t)bt * N1 + C1_Q + h * HDc + c]
                             : C1[(size_t)bt * N1 + C1_QR + (c - HDc)];
        __nv_bfloat16 hh = __float2bfloat16_rn(qv);
        __nv_bfloat16 ll = __float2bfloat16_rn(qv - __bfloat162float(hh));
        Q2[rowQK + 3 * c] = hh; Q2[rowQK + 3 * c + 1] = hh; Q2[rowQK + 3 * c + 2] = ll;
        float kv = (c < HDc) ? C2[(size_t)bt * N2 + h * HDc + c]
                             : C2[(size_t)bt * N2 + C2_KR + (c - HDc)];
        hh = __float2bfloat16_rn(kv);
        ll = __float2bfloat16_rn(kv - __bfloat162float(hh));
        K2[rowQK + 3 * c] = hh; K2[rowQK + 3 * c + 1] = ll; K2[rowQK + 3 * c + 2] = hh;
    }
    if (c < HDc) {
        float vv = C2[(size_t)bt * N2 + C2_V + h * HDc + c];
        __nv_bfloat16 hh = __float2bfloat16_rn(vv);
        __nv_bfloat16 ll = __float2bfloat16_rn(vv - __bfloat162float(hh));
        size_t base = ((size_t)(b * NHc + h) * 3 * Tc + 3 * t) * HDc + c;
        V2[base] = hh; V2[base + HDc] = ll; V2[base + 2 * HDc] = hh;
    }
}

// ---------------- tensor-core flash attention (validated round 9) ----------------
#define QS_ST 584
#define VS_ST 136
#define PS_ST 200

__global__ void __launch_bounds__(128) mla_attn_tc(
    const __nv_bfloat16* __restrict__ Q2, const __nv_bfloat16* __restrict__ K2,
    const __nv_bfloat16* __restrict__ V2, float* __restrict__ og)
{
    extern __shared__ __nv_bfloat16 sm2[];
    __nv_bfloat16* Qs = sm2;
    __nv_bfloat16* Ks = Qs + 64 * QS_ST;
    __nv_bfloat16* Vs = Ks + 64 * QS_ST;
    __nv_bfloat16* Ps = Vs + 192 * VS_ST;

    const int tid = threadIdx.x, lane = tid & 31, wq = tid >> 5;
    const int q0 = blockIdx.x * 64, h = blockIdx.y, b = blockIdx.z;
    const uint32_t qsb = smem_u32(Qs), ksb = smem_u32(Ks), vsb = smem_u32(Vs), psb = smem_u32(Ps);

    const __nv_bfloat16* Qg = Q2 + ((size_t)(b * NHc + h) * Tc + q0) * QK_K;
    const __nv_bfloat16* Kg = K2 + ((size_t)(b * NHc + h) * Tc) * QK_K;
    const __nv_bfloat16* Vg = V2 + ((size_t)(b * NHc + h) * 3 * Tc) * HDc;

#pragma unroll
    for (int i = 0; i < 36; i++) {
        int idx = tid + i * 128, r = idx / 72, seg = idx % 72;
        cp16(qsb + (r * QS_ST + seg * 8) * 2, Qg + (size_t)r * QK_K + seg * 8);
    }
    CP_COMMIT();

    float m0 = -INFINITY, m1 = -INFINITY, l0 = 0.f, l1 = 0.f;
    float oacc[16][4];
#pragma unroll
    for (int i = 0; i < 16; i++)
#pragma unroll
        for (int j = 0; j < 4; j++) oacc[i][j] = 0.f;

    const float inv_scale = 0.0721687836487032f;
    const int arow = wq * 16 + (lane & 15);
    const int acol = (lane >> 4) << 3;
    const int brow_k = ((lane >> 4) << 3) + (lane & 7);
    const int bcol_k = ((lane >> 3) & 1) << 3;
    const int r0l = lane >> 2;
    const int cgrp = (lane & 3) * 2;

    const int ntiles = blockIdx.x + 1;
    for (int jt = 0; jt < ntiles; jt++) {
        const __nv_bfloat16* Kt = Kg + (size_t)jt * 64 * QK_K;
#pragma unroll
        for (int i = 0; i < 36; i++) {
            int idx = tid + i * 128, r = idx / 72, seg = idx % 72;
            cp16(ksb + (r * QS_ST + seg * 8) * 2, Kt + (size_t)r * QK_K + seg * 8);
        }
        CP_COMMIT();
        const __nv_bfloat16* Vt = Vg + (size_t)jt * 192 * HDc;
#pragma unroll
        for (int i = 0; i < 24; i++) {
            int idx = tid + i * 128, r = idx >> 4, seg = idx & 15;
            cp16(vsb + (r * VS_ST + seg * 8) * 2, Vt + (size_t)r * HDc + seg * 8);
        }
        CP_COMMIT();
        CP_WAIT1();
        __syncthreads();

        float sacc[8][4];
#pragma unroll
        for (int i = 0; i < 8; i++)
#pragma unroll
            for (int j = 0; j < 4; j++) sacc[i][j] = 0.f;
#pragma unroll 4
        for (int ks = 0; ks < 36; ks++) {
            uint32_t a[4];
            LDSM4(a, qsb + (arow * QS_ST + ks * 16 + acol) * 2);
#pragma unroll
            for (int nj = 0; nj < 4; nj++) {
                uint32_t r4[4];
                LDSM4(r4, ksb + ((nj * 16 + brow_k) * QS_ST + ks * 16 + bcol_k) * 2);
                MMA16816BF(sacc[2 * nj],     a, r4[0], r4[1]);
                MMA16816BF(sacc[2 * nj + 1], a, r4[2], r4[3]);
            }
        }

        const int qrow0 = q0 + wq * 16 + r0l, qrow1 = qrow0 + 8;
        const int s0 = jt * 64;
        const bool diag = (jt == blockIdx.x);
        float mt0 = -INFINITY, mt1 = -INFINITY;
#pragma unroll
        for (int ni = 0; ni < 8; ni++) {
            float v0 = sacc[ni][0] * inv_scale, v1 = sacc[ni][1] * inv_scale;
            float v2 = sacc[ni][2] * inv_scale, v3 = sacc[ni][3] * inv_scale;
            if (diag) {
                int c = s0 + ni * 8 + cgrp;
                if (c > qrow0)     v0 = -INFINITY;
                if (c + 1 > qrow0) v1 = -INFINITY;
                if (c > qrow1)     v2 = -INFINITY;
                if (c + 1 > qrow1) v3 = -INFINITY;
            }
            sacc[ni][0] = v0; sacc[ni][1] = v1; sacc[ni][2] = v2; sacc[ni][3] = v3;
            mt0 = fmaxf(mt0, fmaxf(v0, v1));
            mt1 = fmaxf(mt1, fmaxf(v2, v3));
        }
        mt0 = fmaxf(mt0, __shfl_xor_sync(0xffffffffu, mt0, 1));
        mt0 = fmaxf(mt0, __shfl_xor_sync(0xffffffffu, mt0, 2));
        mt1 = fmaxf(mt1, __shfl_xor_sync(0xffffffffu, mt1, 1));
        mt1 = fmaxf(mt1, __shfl_xor_sync(0xffffffffu, mt1, 2));
        float nm0 = fmaxf(m0, mt0), nm1 = fmaxf(m1, mt1);
        float f0 = __expf(m0 - nm0), f1 = __expf(m1 - nm1);
        float rs0 = 0.f, rs1 = 0.f;
#pragma unroll
        for (int ni = 0; ni < 8; ni++) {
            float p0 = __expf(sacc[ni][0] - nm0);
            float p1 = __expf(sacc[ni][1] - nm0);
            float p2 = __expf(sacc[ni][2] - nm1);
            float p3 = __expf(sacc[ni][3] - nm1);
            rs0 += p0 + p1; rs1 += p2 + p3;
            __nv_bfloat16 h0 = __float2bfloat16_rn(p0);
            __nv_bfloat16 h1 = __float2bfloat16_rn(p1);
            __nv_bfloat16 h2 = __float2bfloat16_rn(p2);
            __nv_bfloat16 h3 = __float2bfloat16_rn(p3);
            float L0 = p0 - __bfloat162float(h0), L1 = p1 - __bfloat162float(h1);
            float L2 = p2 - __bfloat162float(h2), L3 = p3 - __bfloat162float(h3);
            float F0 = __bfloat162float(h0), F1 = __bfloat162float(h1);
            float F2 = __bfloat162float(h2), F3 = __bfloat162float(h3);
            int cl = ni * 8 + cgrp;
            uint32_t b0 = psb + ((wq * 16 + r0l) * PS_ST + 3 * cl) * 2;
            STS32(b0,     bfpack(F0, F0));
            STS32(b0 + 4, bfpack(L0, F1));
            STS32(b0 + 8, bfpack(F1, L1));
            uint32_t b1 = b0 + 8 * PS_ST * 2;
            STS32(b1,     bfpack(F2, F2));
            STS32(b1 + 4, bfpack(L2, F3));
            STS32(b1 + 8, bfpack(F3, L3));
        }
        rs0 += __shfl_xor_sync(0xffffffffu, rs0, 1);
        rs0 += __shfl_xor_sync(0xffffffffu, rs0, 2);
        rs1 += __shfl_xor_sync(0xffffffffu, rs1, 1);
        rs1 += __shfl_xor_sync(0xffffffffu, rs1, 2);
        l0 = l0 * f0 + rs0; l1 = l1 * f1 + rs1;
        m0 = nm0; m1 = nm1;
#pragma unroll
        for (int ni = 0; ni < 16; ni++) {
            oacc[ni][0] *= f0; oacc[ni][1] *= f0;
            oacc[ni][2] *= f1; oacc[ni][3] *= f1;
        }
        __syncwarp();

        CP_WAIT0();
        __syncthreads();
#pragma unroll
        for (int ks = 0; ks < 12; ks++) {
            uint32_t a[4];
            LDSM4(a, psb + (arow * PS_ST + ks * 16 + acol) * 2);
#pragma unroll
            for (int nj = 0; nj < 8; nj++) {
                uint32_t r4[4];
                LDSM4T(r4, vsb + ((ks * 16 + (lane & 15)) * VS_ST + nj * 16 + acol) * 2);
                MMA16816BF(oacc[2 * nj],     a, r4[0], r4[1]);
                MMA16816BF(oacc[2 * nj + 1], a, r4[2], r4[3]);
            }
        }
        __syncthreads();
    }

    float il0 = 1.0f / l0, il1 = 1.0f / l1;
    int row0 = q0 + wq * 16 + r0l, row1 = row0 + 8;
#pragma unroll
    for (int ni = 0; ni < 16; ni++) {
        int col = h * HDc + ni * 8 + cgrp;
        *(float2*)(og + ((size_t)b * Tc + row0) * Dc + col) =
            make_float2(oacc[ni][0] * il0, oacc[ni][1] * il0);
        *(float2*)(og + ((size_t)b * Tc + row1) * Dc + col) =
            make_float2(oacc[ni][2] * il1, oacc[ni][3] * il1);
    }
}

// ---------------- launch ---------------------------------------------------------
extern "C" void kernel_launch(void* const* d_in, const int* in_sizes, int n_in,
                              void* d_out, int out_size) {
    const float* x    = (const float*)d_in[0];
    const float* Wkv  = (const float*)d_in[1];
    const float* Wkup = (const float*)d_in[2];
    const float* Wvup = (const float*)d_in[3];
    const float* Wq   = (const float*)d_in[4];
    const float* Wqr  = (const float*)d_in[5];
    const float* Wkr  = (const float*)d_in[6];
    const float* Wo   = (const float*)d_in[7];
    float* out      = (float*)d_out;
    float* outEntry = out + (size_t)BT * Dc;

    float *C1, *C2, *att;
    __half *x2, *ckv2, *att2, *wc1, *wc2, *wo;
    __nv_bfloat16 *Q2, *K2, *V2;
    cudaGetSymbolAddress((void**)&C1,   g_C1);
    cudaGetSymbolAddress((void**)&C2,   g_C2);
    cudaGetSymbolAddress((void**)&att,  g_att);
    cudaGetSymbolAddress((void**)&x2,   g_x2);
    cudaGetSymbolAddress((void**)&ckv2, g_ckv2);
    cudaGetSymbolAddress((void**)&att2, g_att2);
    cudaGetSymbolAddress((void**)&wc1,  w_cat1);
    cudaGetSymbolAddress((void**)&wc2,  w_cat2);
    cudaGetSymbolAddress((void**)&wo,   w_o);
    cudaGetSymbolAddress((void**)&Q2,   g_Q2);
    cudaGetSymbolAddress((void**)&K2,   g_K2);
    cudaGetSymbolAddress((void**)&V2,   g_V2);

    const int SMG = GNST * (128 + 128) * 72 * 2;   // 110592
    cudaFuncSetAttribute(gemm_mma, cudaFuncAttributeMaxDynamicSharedMemorySize, SMG);
    const int SMATT = (2 * 64 * QS_ST + 192 * VS_ST + 64 * PS_ST) * 2;  // 227328
    cudaFuncSetAttribute(mla_attn_tc, cudaFuncAttributeMaxDynamicSharedMemorySize, SMATT);

    dim3 tb(32, 8);
    // weight transpose + fp16 hi-dup into concatenated buffers (padding rows stay 0)
    tsplit2<<<dim3(DCc / 32, Dc  / 32), tb>>>(Wkv,  wc1,                        Dc,  DCc);
    tsplit2<<<dim3(Dc  / 32, Dc  / 32), tb>>>(Wq,   wc1 + (size_t)C1_Q  * K2D, Dc,  Dc);
    tsplit2<<<dim3(DRc / 32, Dc  / 32), tb>>>(Wqr,  wc1 + (size_t)C1_QR * K2D, Dc,  DRc);
    tsplit2<<<dim3(Dc  / 32, DCc / 32), tb>>>(Wkup, wc2,                        DCc, Dc);
    tsplit2<<<dim3(Dc  / 32, DCc / 32), tb>>>(Wvup, wc2 + (size_t)C2_V  * K2C, DCc, Dc);
    tsplit2<<<dim3(DRc / 32, DCc / 32), tb>>>(Wkr,  wc2 + (size_t)C2_KR * K2C, DCc, DRc);
    tsplit2<<<dim3(Dc  / 32, Dc  / 32), tb>>>(Wo,   wo,                         Dc,  Dc);
    // activation fp16 2-term split
    split2s<<<(BT * Dc + 255) / 256, 256>>>(x, Dc, x2, BT * Dc, Dc);

    // GEMM1: C1 = x2 @ [Wkv|Wq|Wqr]    (K = 4096)
    gemm_mma<<<dim3(N1 / 128, BT / 128), 256, SMG>>>(x2, wc1, C1, BT, N1, K2D);
    // split ckv (cols 0..511 of C1)
    split2s<<<(BT * DCc + 255) / 256, 256>>>(C1, N1, ckv2, BT * DCc, DCc);
    // GEMM2: C2 = ckv2 @ [Wkup|Wvup|Wkr]   (K = 1024)
    gemm_mma<<<dim3(N2 / 128, BT / 128), 256, SMG>>>(ckv2, wc2, C2, BT, N2, K2C);

    // rope on kr (C2) and qr (C1), then entry output
    rope_kernel<<<BT, 64>>>(C2 + C2_KR, N2, C1 + C1_QR, N1);
    write_entry<<<(BT * (DCc + DRc) + 255) / 256, 256>>>(C1, C2, outEntry);

    // attention (bf16 3-term, unchanged)
    prep_attn<<<BT * NHc, 192>>>(C1, C2, Q2, K2, V2);
    mla_attn_tc<<<dim3(Tc / 64, NHc, Bc), 128, SMATT>>>(Q2, K2, V2, att);

    // output projection (K = 4096)
    split2s<<<(BT * Dc + 255) / 256, 256>>>(att, Dc, att2, BT * Dc, Dc);
    gemm_mma<<<dim3(Dc / 128, BT / 128), 256, SMG>>>(att2, wo, out, BT, Dc, K2D);
}